// round 6
// baseline (speedup 1.0000x reference)
#include <cuda_runtime.h>
#include <cuda_bf16.h>
#include <stdint.h>
#include <math.h>

#define BB 4
#define SS 4096
#define DD 1024
#define MPROJ (BB*SS)

// ---------------- device scratch ----------------
__device__ __nv_bfloat16 g_xh[(size_t)MPROJ*DD], g_xl[(size_t)MPROJ*DD];
__device__ __nv_bfloat16 g_wth[(size_t)3*DD*DD], g_wtl[(size_t)3*DD*DD];
__device__ __nv_bfloat16 g_qh[(size_t)MPROJ*DD], g_ql[(size_t)MPROJ*DD];
__device__ __nv_bfloat16 g_kh[(size_t)MPROJ*DD], g_kl[(size_t)MPROJ*DD];
__device__ __nv_bfloat16 g_vh[(size_t)MPROJ*DD], g_vl[(size_t)MPROJ*DD];
__device__ __nv_bfloat16 g_vth[(size_t)MPROJ*DD], g_vtl[(size_t)MPROJ*DD];
__device__ __nv_bfloat16 g_ph[(size_t)BB*SS*SS], g_pl[(size_t)BB*SS*SS];
__device__ float         g_part[(size_t)BB*SS*32];
__device__ float         g_rsum[(size_t)BB*SS];

// ---------------- PTX helpers (sm_80-level; no 'a'-suffix features) ----------------
__device__ __forceinline__ uint32_t smem_u32(const void* p) {
    uint32_t a;
    asm("{ .reg .u64 t; cvta.to.shared.u64 t, %1; cvt.u32.u64 %0, t; }" : "=r"(a) : "l"(p));
    return a;
}
__device__ __forceinline__ void cp_async16(uint32_t dst, const void* src) {
    asm volatile("cp.async.cg.shared.global [%0], [%1], 16;" :: "r"(dst), "l"(src));
}
__device__ __forceinline__ void cp_commit() {
    asm volatile("cp.async.commit_group;" ::: "memory");
}
template <int N>
__device__ __forceinline__ void cp_wait() {
    asm volatile("cp.async.wait_group %0;" :: "n"(N) : "memory");
}
__device__ __forceinline__ void ldsm_x4(uint32_t* r, uint32_t addr) {
    asm volatile("ldmatrix.sync.aligned.m8n8.x4.shared.b16 {%0,%1,%2,%3}, [%4];"
                 : "=r"(r[0]), "=r"(r[1]), "=r"(r[2]), "=r"(r[3]) : "r"(addr));
}
__device__ __forceinline__ void mma16816(float* c, const uint32_t* a, const uint32_t* b) {
    asm volatile(
        "mma.sync.aligned.m16n8k16.row.col.f32.bf16.bf16.f32 "
        "{%0,%1,%2,%3}, {%4,%5,%6,%7}, {%8,%9}, {%0,%1,%2,%3};"
        : "+f"(c[0]), "+f"(c[1]), "+f"(c[2]), "+f"(c[3])
        : "r"(a[0]), "r"(a[1]), "r"(a[2]), "r"(a[3]), "r"(b[0]), "r"(b[1]));
}
__device__ __forceinline__ void pack_split(float v0, float v1, uint32_t& hp, uint32_t& lp) {
    __nv_bfloat16 h0 = __float2bfloat16(v0);
    __nv_bfloat16 h1 = __float2bfloat16(v1);
    __nv_bfloat16 l0 = __float2bfloat16(v0 - __bfloat162float(h0));
    __nv_bfloat16 l1 = __float2bfloat16(v1 - __bfloat162float(h1));
    hp = (uint32_t)__bfloat16_as_ushort(h0) | ((uint32_t)__bfloat16_as_ushort(h1) << 16);
    lp = (uint32_t)__bfloat16_as_ushort(l0) | ((uint32_t)__bfloat16_as_ushort(l1) << 16);
}

// ---------------- GEMM config ----------------
#define GBM 128
#define GBN 128
#define GBK 64
#define MATB (128*128)
#define STAGEB (4*MATB)
#define NSTAGE 3
#define GEMM_SMEM (NSTAGE*STAGEB)

__device__ __forceinline__ void stage_in(
    const __nv_bfloat16* Ah, const __nv_bfloat16* Al,
    const __nv_bfloat16* Bh, const __nv_bfloat16* Bl,
    int ldA, int ldB, int m0, int n0, int k0, uint32_t sb, int tid)
{
#pragma unroll
    for (int i = 0; i < 4; ++i) {
        const int idx = tid + i * 256;
        const int r = idx >> 3, c16 = idx & 7;
        const uint32_t soff = (uint32_t)(r * 128 + (((c16 ^ (r & 7)) << 4)));
        const size_t ga = (size_t)(m0 + r) * ldA + k0 + c16 * 8;
        const size_t gb = (size_t)(n0 + r) * ldB + k0 + c16 * 8;
        cp_async16(sb + 0 * MATB + soff, Ah + ga);
        cp_async16(sb + 1 * MATB + soff, Al + ga);
        cp_async16(sb + 2 * MATB + soff, Bh + gb);
        cp_async16(sb + 3 * MATB + soff, Bl + gb);
    }
}

// load all fragments for one kc into the given buffers
__device__ __forceinline__ void ld_frags(
    uint32_t sbuf, int kc,
    uint32_t a_off, uint32_t a_rl, uint32_t a_hi4,
    uint32_t b_off, uint32_t b_rl, uint32_t b_hi,
    uint32_t (*ah)[4], uint32_t (*al)[4], uint32_t (*bh)[2], uint32_t (*bl)[2])
{
    const uint32_t a_x = ((((uint32_t)(kc * 2) + a_hi4) ^ a_rl) << 4);
    const uint32_t abase = sbuf + a_off + a_x;
#pragma unroll
    for (int mt = 0; mt < 4; ++mt) {
        ldsm_x4(ah[mt], abase + mt * (16 * 128));
        ldsm_x4(al[mt], abase + MATB + mt * (16 * 128));
    }
    const uint32_t b_x = ((((uint32_t)(kc * 2) + b_hi) ^ b_rl) << 4);
    const uint32_t bbase = sbuf + 2 * MATB + b_off + b_x;
    ldsm_x4(&bh[0][0], bbase);
    ldsm_x4(&bh[2][0], bbase + 16 * 128);
    ldsm_x4(&bl[0][0], bbase + MATB);
    ldsm_x4(&bl[2][0], bbase + MATB + 16 * 128);
}

__device__ __forceinline__ void do_mmas(
    float (*acc)[4][4],
    uint32_t (*ah)[4], uint32_t (*al)[4], uint32_t (*bh)[2], uint32_t (*bl)[2])
{
#pragma unroll
    for (int mt = 0; mt < 4; ++mt)
#pragma unroll
        for (int nt = 0; nt < 4; ++nt) mma16816(acc[mt][nt], ah[mt], bh[nt]);
#pragma unroll
    for (int mt = 0; mt < 4; ++mt)
#pragma unroll
        for (int nt = 0; nt < 4; ++nt) mma16816(acc[mt][nt], al[mt], bh[nt]);
#pragma unroll
    for (int mt = 0; mt < 4; ++mt)
#pragma unroll
        for (int nt = 0; nt < 4; ++nt) mma16816(acc[mt][nt], ah[mt], bl[nt]);
}

// MODE 1: split-bf16 outputs routed among 3 target pairs (projection)
// MODE 2: C fp32 = alpha * D / rsum[row]                     (PV)
// MODE 3: P = exp(alpha*D) split-bf16 + per-(row,ctaX) partial sums (QK+softmax)
template <int MODE>
__global__ void __launch_bounds__(256, 1)
tc_gemm(const __nv_bfloat16* __restrict__ Ahi, const __nv_bfloat16* __restrict__ Alo,
        const __nv_bfloat16* __restrict__ Bhi, const __nv_bfloat16* __restrict__ Blo,
        float* __restrict__ Cf,
        __nv_bfloat16* __restrict__ o0h, __nv_bfloat16* __restrict__ o0l,
        __nv_bfloat16* __restrict__ o1h, __nv_bfloat16* __restrict__ o1l,
        __nv_bfloat16* __restrict__ o2h, __nv_bfloat16* __restrict__ o2l,
        int M, int N, int K, int ldA, int ldB,
        size_t zA, size_t zB, size_t zC,
        float alpha, const float* __restrict__ rsum, float* __restrict__ part)
{
    extern __shared__ __align__(128) char smem[];
    const uint32_t sbase = smem_u32(smem);
    const int tid = threadIdx.x;
    const int wid = tid >> 5, lane = tid & 31;
    const int wm = wid >> 2, wn = wid & 3;
    const int z = blockIdx.z;
    const int m0 = blockIdx.y * GBM, n0 = blockIdx.x * GBN;

    Ahi += (size_t)z * zA;  Alo += (size_t)z * zA;
    Bhi += (size_t)z * zB;  Blo += (size_t)z * zB;

    float acc[4][4][4];
#pragma unroll
    for (int i = 0; i < 4; ++i)
#pragma unroll
        for (int j = 0; j < 4; ++j)
#pragma unroll
            for (int q = 0; q < 4; ++q) acc[i][j][q] = 0.f;

    const int numT = K / GBK;

    stage_in(Ahi, Alo, Bhi, Blo, ldA, ldB, m0, n0, 0, sbase, tid);
    cp_commit();
    stage_in(Ahi, Alo, Bhi, Blo, ldA, ldB, m0, n0, GBK, sbase + STAGEB, tid);
    cp_commit();

    const int a_row = wm * 64 + (lane & 15);
    const uint32_t a_rl = (uint32_t)(a_row & 7);
    const uint32_t a_hi4 = (uint32_t)(lane >> 4);
    const uint32_t a_off = (uint32_t)(a_row * 128);

    const int b_row = wn * 32 + ((lane >> 4) & 1) * 8 + (lane & 7);
    const uint32_t b_rl = (uint32_t)(b_row & 7);
    const uint32_t b_hi = (uint32_t)((lane >> 3) & 1);
    const uint32_t b_off = (uint32_t)(b_row * 128);

    // double-buffered fragments
    uint32_t ah[2][4][4], al[2][4][4], bh[2][4][2], bl[2][4][2];

    int sidx = 0;
    for (int t = 0; t < numT; ++t) {
        cp_wait<1>();
        __syncthreads();

        const uint32_t sbuf = sbase + sidx * STAGEB;

        // prime fragments for kc = 0
        ld_frags(sbuf, 0, a_off, a_rl, a_hi4, b_off, b_rl, b_hi,
                 ah[0], al[0], bh[0], bl[0]);

        if (t + 2 < numT) {
            int ws = sidx + 2; if (ws >= NSTAGE) ws -= NSTAGE;
            stage_in(Ahi, Alo, Bhi, Blo, ldA, ldB, m0, n0, (t + 2) * GBK,
                     sbase + ws * STAGEB, tid);
        }

#pragma unroll
        for (int kc = 0; kc < 4; ++kc) {
            const int cur = kc & 1;
            if (kc < 3)
                ld_frags(sbuf, kc + 1, a_off, a_rl, a_hi4, b_off, b_rl, b_hi,
                         ah[cur ^ 1], al[cur ^ 1], bh[cur ^ 1], bl[cur ^ 1]);
            do_mmas(acc, ah[cur], al[cur], bh[cur], bl[cur]);
        }

        cp_commit();
        if (++sidx == NSTAGE) sidx = 0;
    }

    // ---------------- epilogue ----------------
    const int qrow = lane >> 2;
    const int qcol = (lane & 3) * 2;

    if (MODE == 3) {
        __syncthreads();
        float* psum = reinterpret_cast<float*>(smem);
        float rsloc[4][2];
#pragma unroll
        for (int mt = 0; mt < 4; ++mt) { rsloc[mt][0] = 0.f; rsloc[mt][1] = 0.f; }

#pragma unroll
        for (int mt = 0; mt < 4; ++mt) {
            const int r0 = m0 + wm * 64 + mt * 16 + qrow;
#pragma unroll
            for (int nt = 0; nt < 4; ++nt) {
                const int ncol = n0 + wn * 32 + nt * 8 + qcol;
                const float* c = acc[mt][nt];
                const float e0 = __expf(alpha * c[0]);
                const float e1 = __expf(alpha * c[1]);
                const float e2 = __expf(alpha * c[2]);
                const float e3 = __expf(alpha * c[3]);
                rsloc[mt][0] += e0 + e1;
                rsloc[mt][1] += e2 + e3;
                uint32_t hp, lp;
                pack_split(e0, e1, hp, lp);
                size_t off = (size_t)z * zC + (size_t)r0 * N + ncol;
                *reinterpret_cast<uint32_t*>(o0h + off) = hp;
                *reinterpret_cast<uint32_t*>(o0l + off) = lp;
                pack_split(e2, e3, hp, lp);
                off += (size_t)8 * N;
                *reinterpret_cast<uint32_t*>(o0h + off) = hp;
                *reinterpret_cast<uint32_t*>(o0l + off) = lp;
            }
        }
#pragma unroll
        for (int mt = 0; mt < 4; ++mt)
#pragma unroll
            for (int h = 0; h < 2; ++h) {
                float v = rsloc[mt][h];
                v += __shfl_xor_sync(0xffffffffu, v, 1);
                v += __shfl_xor_sync(0xffffffffu, v, 2);
                rsloc[mt][h] = v;
            }
        if ((lane & 3) == 0) {
#pragma unroll
            for (int mt = 0; mt < 4; ++mt) {
                const int lr = wm * 64 + mt * 16 + qrow;
                psum[wn * GBM + lr] = rsloc[mt][0];
                psum[wn * GBM + lr + 8] = rsloc[mt][1];
            }
        }
        __syncthreads();
        if (tid < GBM) {
            const float s = psum[tid] + psum[GBM + tid] + psum[2 * GBM + tid] + psum[3 * GBM + tid];
            part[((size_t)z * M + m0 + tid) * gridDim.x + blockIdx.x] = s;
        }
        return;
    }

#pragma unroll
    for (int mt = 0; mt < 4; ++mt) {
        const int r0 = m0 + wm * 64 + mt * 16 + qrow;
        float sc0 = alpha, sc1 = alpha;
        if (MODE == 2) {
            sc0 = alpha / __ldg(&rsum[(size_t)z * M + r0]);
            sc1 = alpha / __ldg(&rsum[(size_t)z * M + r0 + 8]);
        }
#pragma unroll
        for (int nt = 0; nt < 4; ++nt) {
            const int ncol = n0 + wn * 32 + nt * 8 + qcol;
            const float* c = acc[mt][nt];
            if (MODE == 2) {
                float* base = Cf + (size_t)z * zC;
                float2 v0 = make_float2(sc0 * c[0], sc0 * c[1]);
                float2 v1 = make_float2(sc1 * c[2], sc1 * c[3]);
                *reinterpret_cast<float2*>(base + (size_t)r0 * N + ncol) = v0;
                *reinterpret_cast<float2*>(base + (size_t)(r0 + 8) * N + ncol) = v1;
            } else {   // MODE 1
                const int sel = ncol >> 10;
                __nv_bfloat16* Dh = (sel == 0) ? o0h : ((sel == 1) ? o1h : o2h);
                __nv_bfloat16* Dl = (sel == 0) ? o0l : ((sel == 1) ? o1l : o2l);
                const int cm = ncol & (DD - 1);
                uint32_t hp, lp;
                pack_split(c[0], c[1], hp, lp);
                size_t off = (size_t)r0 * DD + cm;
                *reinterpret_cast<uint32_t*>(Dh + off) = hp;
                *reinterpret_cast<uint32_t*>(Dl + off) = lp;
                pack_split(c[2], c[3], hp, lp);
                off += (size_t)8 * DD;
                *reinterpret_cast<uint32_t*>(Dh + off) = hp;
                *reinterpret_cast<uint32_t*>(Dl + off) = lp;
            }
        }
    }
}

// ---------------- aux kernels ----------------
__global__ __launch_bounds__(256)
void split_f32(const float* __restrict__ in, __nv_bfloat16* __restrict__ hi,
               __nv_bfloat16* __restrict__ lo, size_t n4)
{
    size_t i = (size_t)blockIdx.x * 256 + threadIdx.x;
    if (i >= n4) return;
    float4 v = reinterpret_cast<const float4*>(in)[i];
    uint32_t h0, l0, h1, l1;
    pack_split(v.x, v.y, h0, l0);
    pack_split(v.z, v.w, h1, l1);
    reinterpret_cast<uint2*>(hi)[i] = make_uint2(h0, h1);
    reinterpret_cast<uint2*>(lo)[i] = make_uint2(l0, l1);
}

__global__ __launch_bounds__(256)
void split_w_t(const float* __restrict__ Wq, const float* __restrict__ Wk,
               const float* __restrict__ Wv,
               __nv_bfloat16* __restrict__ th, __nv_bfloat16* __restrict__ tl)
{
    __shared__ float tile[32][33];
    const int zz = blockIdx.z;
    const float* W = (zz == 0) ? Wq : ((zz == 1) ? Wk : Wv);
    const int k0 = blockIdx.x * 32;
    const int n0 = blockIdx.y * 32;
    const int lx = threadIdx.x & 31, ly = threadIdx.x >> 5;
#pragma unroll
    for (int i = 0; i < 32; i += 8)
        tile[ly + i][lx] = W[(size_t)(k0 + ly + i) * DD + n0 + lx];
    __syncthreads();
#pragma unroll
    for (int i = 0; i < 32; i += 8) {
        float v = tile[lx][ly + i];
        __nv_bfloat16 h = __float2bfloat16(v);
        __nv_bfloat16 l = __float2bfloat16(v - __bfloat162float(h));
        size_t o = ((size_t)zz * DD + (n0 + ly + i)) * DD + k0 + lx;
        th[o] = h;
        tl[o] = l;
    }
}

__global__ __launch_bounds__(256)
void transpose_v(const __nv_bfloat16* __restrict__ vh, const __nv_bfloat16* __restrict__ vl,
                 __nv_bfloat16* __restrict__ vth, __nv_bfloat16* __restrict__ vtl)
{
    __shared__ __nv_bfloat16 t0[32][33], t1[32][33];
    const int b = blockIdx.z;
    const int s0 = blockIdx.x * 32, d0 = blockIdx.y * 32;
    const int lx = threadIdx.x & 31, ly = threadIdx.x >> 5;
#pragma unroll
    for (int i = 0; i < 32; i += 8) {
        size_t src = ((size_t)b * SS + s0 + ly + i) * DD + d0 + lx;
        t0[ly + i][lx] = vh[src];
        t1[ly + i][lx] = vl[src];
    }
    __syncthreads();
#pragma unroll
    for (int i = 0; i < 32; i += 8) {
        size_t dst = (size_t)b * SS * DD + (size_t)(d0 + ly + i) * SS + s0 + lx;
        vth[dst] = t0[lx][ly + i];
        vtl[dst] = t1[lx][ly + i];
    }
}

__global__ __launch_bounds__(256)
void reduce_rsum(const float* __restrict__ part, float* __restrict__ rsum)
{
    const int row = blockIdx.x * 8 + (threadIdx.x >> 5);
    const int lane = threadIdx.x & 31;
    float v = part[(size_t)row * 32 + lane];
#pragma unroll
    for (int o = 16; o > 0; o >>= 1) v += __shfl_xor_sync(0xffffffffu, v, o);
    if (lane == 0) rsum[row] = v;
}

// ---------------- launch ----------------
extern "C" void kernel_launch(void* const* d_in, const int* in_sizes, int n_in,
                              void* d_out, int out_size)
{
    const float* x  = (const float*)d_in[0];
    const float* Wq = (const float*)d_in[1];
    const float* Wk = (const float*)d_in[2];
    const float* Wv = (const float*)d_in[3];
    float* out = (float*)d_out;

    __nv_bfloat16 *pxh, *pxl, *pwth, *pwtl, *pqh, *pql, *pkh, *pkl, *pvh, *pvl, *pvth, *pvtl, *pph, *ppl;
    float *prs, *ppart;
    cudaGetSymbolAddress((void**)&pxh, g_xh);   cudaGetSymbolAddress((void**)&pxl, g_xl);
    cudaGetSymbolAddress((void**)&pwth, g_wth); cudaGetSymbolAddress((void**)&pwtl, g_wtl);
    cudaGetSymbolAddress((void**)&pqh, g_qh);   cudaGetSymbolAddress((void**)&pql, g_ql);
    cudaGetSymbolAddress((void**)&pkh, g_kh);   cudaGetSymbolAddress((void**)&pkl, g_kl);
    cudaGetSymbolAddress((void**)&pvh, g_vh);   cudaGetSymbolAddress((void**)&pvl, g_vl);
    cudaGetSymbolAddress((void**)&pvth, g_vth); cudaGetSymbolAddress((void**)&pvtl, g_vtl);
    cudaGetSymbolAddress((void**)&pph, g_ph);   cudaGetSymbolAddress((void**)&ppl, g_pl);
    cudaGetSymbolAddress((void**)&prs, g_rsum); cudaGetSymbolAddress((void**)&ppart, g_part);

    cudaFuncSetAttribute(tc_gemm<1>, cudaFuncAttributeMaxDynamicSharedMemorySize, GEMM_SMEM);
    cudaFuncSetAttribute(tc_gemm<2>, cudaFuncAttributeMaxDynamicSharedMemorySize, GEMM_SMEM);
    cudaFuncSetAttribute(tc_gemm<3>, cudaFuncAttributeMaxDynamicSharedMemorySize, GEMM_SMEM);

    // 1) split inputs
    split_f32<<<(unsigned)(((size_t)MPROJ * DD / 4 + 255) / 256), 256>>>(x, pxh, pxl, (size_t)MPROJ * DD / 4);
    split_w_t<<<dim3(DD / 32, DD / 32, 3), 256>>>(Wq, Wk, Wv, pwth, pwtl);

    // 2) fused QKV projection
    tc_gemm<1><<<dim3(3 * DD / GBN, MPROJ / GBM, 1), 256, GEMM_SMEM>>>(
        pxh, pxl, pwth, pwtl, nullptr,
        pqh, pql, pkh, pkl, pvh, pvl,
        MPROJ, 3 * DD, DD, DD, DD, 0, 0, 0, 1.0f, nullptr, nullptr);

    // 3) V transpose (per batch)
    transpose_v<<<dim3(SS / 32, DD / 32, BB), 256>>>(pvh, pvl, pvth, pvtl);

    // 4) QK^T + fused exp/split + row partial sums
    tc_gemm<3><<<dim3(SS / GBN, SS / GBM, BB), 256, GEMM_SMEM>>>(
        pqh, pql, pkh, pkl, nullptr,
        pph, ppl, nullptr, nullptr, nullptr, nullptr,
        SS, SS, DD, DD, DD,
        (size_t)SS * DD, (size_t)SS * DD, (size_t)SS * SS, 1.0f / 32.0f, nullptr, ppart);

    // 5) reduce partials -> rsum
    reduce_rsum<<<BB * SS / 8, 256>>>(ppart, prs);

    // 6) out = (P @ Vt^T) / rsum per batch
    tc_gemm<2><<<dim3(DD / GBN, SS / GBM, BB), 256, GEMM_SMEM>>>(
        pph, ppl, pvth, pvtl, out,
        nullptr, nullptr, nullptr, nullptr, nullptr, nullptr,
        SS, DD, SS, SS, SS,
        (size_t)SS * SS, (size_t)SS * DD, (size_t)SS * DD, 1.0f, prs, nullptr);
}

// round 7
// speedup vs baseline: 1.0129x; 1.0129x over previous
#include <cuda_runtime.h>
#include <cuda_bf16.h>
#include <stdint.h>
#include <math.h>

#define BB 4
#define SS 4096
#define DD 1024
#define MPROJ (BB*SS)

// ---------------- device scratch ----------------
__device__ __nv_bfloat16 g_xh[(size_t)MPROJ*DD], g_xl[(size_t)MPROJ*DD];
__device__ __nv_bfloat16 g_wth[(size_t)3*DD*DD], g_wtl[(size_t)3*DD*DD];
__device__ __nv_bfloat16 g_qh[(size_t)MPROJ*DD], g_ql[(size_t)MPROJ*DD];
__device__ __nv_bfloat16 g_kh[(size_t)MPROJ*DD], g_kl[(size_t)MPROJ*DD];
__device__ __nv_bfloat16 g_vh[(size_t)MPROJ*DD], g_vl[(size_t)MPROJ*DD];
__device__ __nv_bfloat16 g_vth[(size_t)MPROJ*DD], g_vtl[(size_t)MPROJ*DD];
__device__ __nv_bfloat16 g_ph[(size_t)BB*SS*SS], g_pl[(size_t)BB*SS*SS];
__device__ float         g_part[(size_t)BB*SS*32];
__device__ float         g_rsum[(size_t)BB*SS];

// ---------------- PTX helpers (sm_80-level; no 'a'-suffix features) ----------------
__device__ __forceinline__ uint32_t smem_u32(const void* p) {
    uint32_t a;
    asm("{ .reg .u64 t; cvta.to.shared.u64 t, %1; cvt.u32.u64 %0, t; }" : "=r"(a) : "l"(p));
    return a;
}
__device__ __forceinline__ void cp_async16(uint32_t dst, const void* src) {
    asm volatile("cp.async.cg.shared.global [%0], [%1], 16;" :: "r"(dst), "l"(src));
}
__device__ __forceinline__ void cp_commit() {
    asm volatile("cp.async.commit_group;" ::: "memory");
}
template <int N>
__device__ __forceinline__ void cp_wait() {
    asm volatile("cp.async.wait_group %0;" :: "n"(N) : "memory");
}
__device__ __forceinline__ void ldsm_x4(uint32_t* r, uint32_t addr) {
    asm volatile("ldmatrix.sync.aligned.m8n8.x4.shared.b16 {%0,%1,%2,%3}, [%4];"
                 : "=r"(r[0]), "=r"(r[1]), "=r"(r[2]), "=r"(r[3]) : "r"(addr));
}
__device__ __forceinline__ void mma16816(float* c, const uint32_t* a, const uint32_t* b) {
    asm volatile(
        "mma.sync.aligned.m16n8k16.row.col.f32.bf16.bf16.f32 "
        "{%0,%1,%2,%3}, {%4,%5,%6,%7}, {%8,%9}, {%0,%1,%2,%3};"
        : "+f"(c[0]), "+f"(c[1]), "+f"(c[2]), "+f"(c[3])
        : "r"(a[0]), "r"(a[1]), "r"(a[2]), "r"(a[3]), "r"(b[0]), "r"(b[1]));
}
__device__ __forceinline__ void pack_split(float v0, float v1, uint32_t& hp, uint32_t& lp) {
    __nv_bfloat16 h0 = __float2bfloat16(v0);
    __nv_bfloat16 h1 = __float2bfloat16(v1);
    __nv_bfloat16 l0 = __float2bfloat16(v0 - __bfloat162float(h0));
    __nv_bfloat16 l1 = __float2bfloat16(v1 - __bfloat162float(h1));
    hp = (uint32_t)__bfloat16_as_ushort(h0) | ((uint32_t)__bfloat16_as_ushort(h1) << 16);
    lp = (uint32_t)__bfloat16_as_ushort(l0) | ((uint32_t)__bfloat16_as_ushort(l1) << 16);
}

// ---------------- GEMM config: CTA 256x128, BK=64, 8 warps (4x2), warp tile 64x64 ----
#define GBM 256
#define GBN 128
#define GBK 64
#define AHI 0
#define ALO 32768
#define BHI 65536
#define BLO 81920
#define STAGEB 98304
#define GEMM_SMEM (2*STAGEB)   // 196608

__device__ __forceinline__ void stage_in(
    const __nv_bfloat16* Ah, const __nv_bfloat16* Al,
    const __nv_bfloat16* Bh, const __nv_bfloat16* Bl,
    int ldA, int ldB, int m0, int n0, int k0, uint32_t sb, int tid)
{
    // A: 256 rows x 8 chunks (hi & lo)
#pragma unroll
    for (int i = 0; i < 8; ++i) {
        const int idx = tid + i * 256;
        const int r = idx >> 3, c16 = idx & 7;
        const uint32_t soff = (uint32_t)(r * 128 + (((c16 ^ (r & 7)) << 4)));
        const size_t ga = (size_t)(m0 + r) * ldA + k0 + c16 * 8;
        cp_async16(sb + AHI + soff, Ah + ga);
        cp_async16(sb + ALO + soff, Al + ga);
    }
    // B: 128 rows x 8 chunks (hi & lo)
#pragma unroll
    for (int i = 0; i < 4; ++i) {
        const int idx = tid + i * 256;
        const int r = idx >> 3, c16 = idx & 7;
        const uint32_t soff = (uint32_t)(r * 128 + (((c16 ^ (r & 7)) << 4)));
        const size_t gb = (size_t)(n0 + r) * ldB + k0 + c16 * 8;
        cp_async16(sb + BHI + soff, Bh + gb);
        cp_async16(sb + BLO + soff, Bl + gb);
    }
}

__device__ __forceinline__ void ld_a4(uint32_t base, uint32_t (*a)[4]) {
#pragma unroll
    for (int mt = 0; mt < 4; ++mt) ldsm_x4(a[mt], base + mt * (16 * 128));
}
__device__ __forceinline__ void ld_b8(uint32_t base, uint32_t (*b)[2]) {
    ldsm_x4(&b[0][0], base);
    ldsm_x4(&b[2][0], base + 16 * 128);
    ldsm_x4(&b[4][0], base + 32 * 128);
    ldsm_x4(&b[6][0], base + 48 * 128);
}
__device__ __forceinline__ void mma_block(float (*acc)[8][4], uint32_t (*a)[4], uint32_t (*b)[2]) {
#pragma unroll
    for (int mt = 0; mt < 4; ++mt)
#pragma unroll
        for (int nt = 0; nt < 8; ++nt) mma16816(acc[mt][nt], a[mt], b[nt]);
}

// MODE 1: split-bf16 outputs routed among 3 target pairs (projection)
// MODE 2: C fp32 = alpha * D / rsum[row]                     (PV)
// MODE 3: P = exp(alpha*D) split-bf16 + per-(row,ctaX) partial sums (QK+softmax)
template <int MODE>
__global__ void __launch_bounds__(256, 1)
tc_gemm(const __nv_bfloat16* __restrict__ Ahi, const __nv_bfloat16* __restrict__ Alo,
        const __nv_bfloat16* __restrict__ Bhi, const __nv_bfloat16* __restrict__ Blo,
        float* __restrict__ Cf,
        __nv_bfloat16* __restrict__ o0h, __nv_bfloat16* __restrict__ o0l,
        __nv_bfloat16* __restrict__ o1h, __nv_bfloat16* __restrict__ o1l,
        __nv_bfloat16* __restrict__ o2h, __nv_bfloat16* __restrict__ o2l,
        int M, int N, int K, int ldA, int ldB,
        size_t zA, size_t zB, size_t zC,
        float alpha, const float* __restrict__ rsum, float* __restrict__ part)
{
    extern __shared__ __align__(128) char smem[];
    const uint32_t sbase = smem_u32(smem);
    const int tid = threadIdx.x;
    const int wid = tid >> 5, lane = tid & 31;
    const int wm = wid >> 1, wn = wid & 1;        // warp grid 4 x 2
    const int z = blockIdx.z;
    const int m0 = blockIdx.y * GBM, n0 = blockIdx.x * GBN;

    Ahi += (size_t)z * zA;  Alo += (size_t)z * zA;
    Bhi += (size_t)z * zB;  Blo += (size_t)z * zB;

    float acc[4][8][4];
#pragma unroll
    for (int i = 0; i < 4; ++i)
#pragma unroll
        for (int j = 0; j < 8; ++j)
#pragma unroll
            for (int q = 0; q < 4; ++q) acc[i][j][q] = 0.f;

    const int numT = K / GBK;

    stage_in(Ahi, Alo, Bhi, Blo, ldA, ldB, m0, n0, 0, sbase, tid);
    cp_commit();

    const int a_row = wm * 64 + (lane & 15);
    const uint32_t a_rl = (uint32_t)(a_row & 7);
    const uint32_t a_hi4 = (uint32_t)(lane >> 4);
    const uint32_t a_off = (uint32_t)(a_row * 128);

    const int b_row = wn * 64 + ((lane >> 4) & 1) * 8 + (lane & 7);
    const uint32_t b_rl = (uint32_t)(b_row & 7);
    const uint32_t b_hi = (uint32_t)((lane >> 3) & 1);
    const uint32_t b_off = (uint32_t)(b_row * 128);

    for (int t = 0; t < numT; ++t) {
        if (t + 1 < numT) {
            stage_in(Ahi, Alo, Bhi, Blo, ldA, ldB, m0, n0, (t + 1) * GBK,
                     sbase + ((t + 1) & 1) * STAGEB, tid);
            cp_commit();
            cp_wait<1>();
        } else {
            cp_wait<0>();
        }
        __syncthreads();

        const uint32_t sbuf = sbase + (t & 1) * STAGEB;
#pragma unroll
        for (int kc = 0; kc < 4; ++kc) {
            uint32_t af[4][4], bf[8][2], af2[4][4];
            const uint32_t a_x = ((((uint32_t)(kc * 2) + a_hi4) ^ a_rl) << 4);
            const uint32_t b_x = ((((uint32_t)(kc * 2) + b_hi) ^ b_rl) << 4);

            ld_a4(sbuf + AHI + a_off + a_x, af);      // A hi
            ld_b8(sbuf + BHI + b_off + b_x, bf);      // B hi
            mma_block(acc, af, bf);                   // hi*hi
            ld_a4(sbuf + ALO + a_off + a_x, af2);     // A lo
            mma_block(acc, af2, bf);                  // lo*hi
            ld_b8(sbuf + BLO + b_off + b_x, bf);      // B lo (reuse regs)
            mma_block(acc, af, bf);                   // hi*lo
        }
        __syncthreads();
    }

    // ---------------- epilogue ----------------
    const int qrow = lane >> 2;
    const int qcol = (lane & 3) * 2;

    if (MODE == 3) {
        float* psum = reinterpret_cast<float*>(smem);
        float rsloc[4][2];
#pragma unroll
        for (int mt = 0; mt < 4; ++mt) { rsloc[mt][0] = 0.f; rsloc[mt][1] = 0.f; }

#pragma unroll
        for (int mt = 0; mt < 4; ++mt) {
            const int r0 = m0 + wm * 64 + mt * 16 + qrow;
#pragma unroll
            for (int nt = 0; nt < 8; ++nt) {
                const int ncol = n0 + wn * 64 + nt * 8 + qcol;
                const float* c = acc[mt][nt];
                const float e0 = __expf(alpha * c[0]);
                const float e1 = __expf(alpha * c[1]);
                const float e2 = __expf(alpha * c[2]);
                const float e3 = __expf(alpha * c[3]);
                rsloc[mt][0] += e0 + e1;
                rsloc[mt][1] += e2 + e3;
                uint32_t hp, lp;
                pack_split(e0, e1, hp, lp);
                size_t off = (size_t)z * zC + (size_t)r0 * N + ncol;
                *reinterpret_cast<uint32_t*>(o0h + off) = hp;
                *reinterpret_cast<uint32_t*>(o0l + off) = lp;
                pack_split(e2, e3, hp, lp);
                off += (size_t)8 * N;
                *reinterpret_cast<uint32_t*>(o0h + off) = hp;
                *reinterpret_cast<uint32_t*>(o0l + off) = lp;
            }
        }
#pragma unroll
        for (int mt = 0; mt < 4; ++mt)
#pragma unroll
            for (int h = 0; h < 2; ++h) {
                float v = rsloc[mt][h];
                v += __shfl_xor_sync(0xffffffffu, v, 1);
                v += __shfl_xor_sync(0xffffffffu, v, 2);
                rsloc[mt][h] = v;
            }
        if ((lane & 3) == 0) {
#pragma unroll
            for (int mt = 0; mt < 4; ++mt) {
                const int lr = wm * 64 + mt * 16 + qrow;
                psum[wn * GBM + lr] = rsloc[mt][0];
                psum[wn * GBM + lr + 8] = rsloc[mt][1];
            }
        }
        __syncthreads();
        if (tid < GBM) {
            const float s = psum[tid] + psum[GBM + tid];
            part[((size_t)z * M + m0 + tid) * gridDim.x + blockIdx.x] = s;
        }
        return;
    }

#pragma unroll
    for (int mt = 0; mt < 4; ++mt) {
        const int r0 = m0 + wm * 64 + mt * 16 + qrow;
        float sc0 = alpha, sc1 = alpha;
        if (MODE == 2) {
            sc0 = alpha / __ldg(&rsum[(size_t)z * M + r0]);
            sc1 = alpha / __ldg(&rsum[(size_t)z * M + r0 + 8]);
        }
#pragma unroll
        for (int nt = 0; nt < 8; ++nt) {
            const int ncol = n0 + wn * 64 + nt * 8 + qcol;
            const float* c = acc[mt][nt];
            if (MODE == 2) {
                float* base = Cf + (size_t)z * zC;
                float2 v0 = make_float2(sc0 * c[0], sc0 * c[1]);
                float2 v1 = make_float2(sc1 * c[2], sc1 * c[3]);
                *reinterpret_cast<float2*>(base + (size_t)r0 * N + ncol) = v0;
                *reinterpret_cast<float2*>(base + (size_t)(r0 + 8) * N + ncol) = v1;
            } else {   // MODE 1
                const int sel = ncol >> 10;
                __nv_bfloat16* Dh = (sel == 0) ? o0h : ((sel == 1) ? o1h : o2h);
                __nv_bfloat16* Dl = (sel == 0) ? o0l : ((sel == 1) ? o1l : o2l);
                const int cm = ncol & (DD - 1);
                uint32_t hp, lp;
                pack_split(c[0], c[1], hp, lp);
                size_t off = (size_t)r0 * DD + cm;
                *reinterpret_cast<uint32_t*>(Dh + off) = hp;
                *reinterpret_cast<uint32_t*>(Dl + off) = lp;
                pack_split(c[2], c[3], hp, lp);
                off += (size_t)8 * DD;
                *reinterpret_cast<uint32_t*>(Dh + off) = hp;
                *reinterpret_cast<uint32_t*>(Dl + off) = lp;
            }
        }
    }
}

// ---------------- aux kernels ----------------
__global__ __launch_bounds__(256)
void split_f32(const float* __restrict__ in, __nv_bfloat16* __restrict__ hi,
               __nv_bfloat16* __restrict__ lo, size_t n4)
{
    size_t i = (size_t)blockIdx.x * 256 + threadIdx.x;
    if (i >= n4) return;
    float4 v = reinterpret_cast<const float4*>(in)[i];
    uint32_t h0, l0, h1, l1;
    pack_split(v.x, v.y, h0, l0);
    pack_split(v.z, v.w, h1, l1);
    reinterpret_cast<uint2*>(hi)[i] = make_uint2(h0, h1);
    reinterpret_cast<uint2*>(lo)[i] = make_uint2(l0, l1);
}

__global__ __launch_bounds__(256)
void split_w_t(const float* __restrict__ Wq, const float* __restrict__ Wk,
               const float* __restrict__ Wv,
               __nv_bfloat16* __restrict__ th, __nv_bfloat16* __restrict__ tl)
{
    __shared__ float tile[32][33];
    const int zz = blockIdx.z;
    const float* W = (zz == 0) ? Wq : ((zz == 1) ? Wk : Wv);
    const int k0 = blockIdx.x * 32;
    const int n0 = blockIdx.y * 32;
    const int lx = threadIdx.x & 31, ly = threadIdx.x >> 5;
#pragma unroll
    for (int i = 0; i < 32; i += 8)
        tile[ly + i][lx] = W[(size_t)(k0 + ly + i) * DD + n0 + lx];
    __syncthreads();
#pragma unroll
    for (int i = 0; i < 32; i += 8) {
        float v = tile[lx][ly + i];
        __nv_bfloat16 h = __float2bfloat16(v);
        __nv_bfloat16 l = __float2bfloat16(v - __bfloat162float(h));
        size_t o = ((size_t)zz * DD + (n0 + ly + i)) * DD + k0 + lx;
        th[o] = h;
        tl[o] = l;
    }
}

__global__ __launch_bounds__(256)
void transpose_v(const __nv_bfloat16* __restrict__ vh, const __nv_bfloat16* __restrict__ vl,
                 __nv_bfloat16* __restrict__ vth, __nv_bfloat16* __restrict__ vtl)
{
    __shared__ __nv_bfloat16 t0[32][33], t1[32][33];
    const int b = blockIdx.z;
    const int s0 = blockIdx.x * 32, d0 = blockIdx.y * 32;
    const int lx = threadIdx.x & 31, ly = threadIdx.x >> 5;
#pragma unroll
    for (int i = 0; i < 32; i += 8) {
        size_t src = ((size_t)b * SS + s0 + ly + i) * DD + d0 + lx;
        t0[ly + i][lx] = vh[src];
        t1[ly + i][lx] = vl[src];
    }
    __syncthreads();
#pragma unroll
    for (int i = 0; i < 32; i += 8) {
        size_t dst = (size_t)b * SS * DD + (size_t)(d0 + ly + i) * SS + s0 + lx;
        vth[dst] = t0[lx][ly + i];
        vtl[dst] = t1[lx][ly + i];
    }
}

__global__ __launch_bounds__(256)
void reduce_rsum(const float* __restrict__ part, float* __restrict__ rsum)
{
    const int row = blockIdx.x * 8 + (threadIdx.x >> 5);
    const int lane = threadIdx.x & 31;
    float v = part[(size_t)row * 32 + lane];
#pragma unroll
    for (int o = 16; o > 0; o >>= 1) v += __shfl_xor_sync(0xffffffffu, v, o);
    if (lane == 0) rsum[row] = v;
}

// ---------------- launch ----------------
extern "C" void kernel_launch(void* const* d_in, const int* in_sizes, int n_in,
                              void* d_out, int out_size)
{
    const float* x  = (const float*)d_in[0];
    const float* Wq = (const float*)d_in[1];
    const float* Wk = (const float*)d_in[2];
    const float* Wv = (const float*)d_in[3];
    float* out = (float*)d_out;

    __nv_bfloat16 *pxh, *pxl, *pwth, *pwtl, *pqh, *pql, *pkh, *pkl, *pvh, *pvl, *pvth, *pvtl, *pph, *ppl;
    float *prs, *ppart;
    cudaGetSymbolAddress((void**)&pxh, g_xh);   cudaGetSymbolAddress((void**)&pxl, g_xl);
    cudaGetSymbolAddress((void**)&pwth, g_wth); cudaGetSymbolAddress((void**)&pwtl, g_wtl);
    cudaGetSymbolAddress((void**)&pqh, g_qh);   cudaGetSymbolAddress((void**)&pql, g_ql);
    cudaGetSymbolAddress((void**)&pkh, g_kh);   cudaGetSymbolAddress((void**)&pkl, g_kl);
    cudaGetSymbolAddress((void**)&pvh, g_vh);   cudaGetSymbolAddress((void**)&pvl, g_vl);
    cudaGetSymbolAddress((void**)&pvth, g_vth); cudaGetSymbolAddress((void**)&pvtl, g_vtl);
    cudaGetSymbolAddress((void**)&pph, g_ph);   cudaGetSymbolAddress((void**)&ppl, g_pl);
    cudaGetSymbolAddress((void**)&prs, g_rsum); cudaGetSymbolAddress((void**)&ppart, g_part);

    cudaFuncSetAttribute(tc_gemm<1>, cudaFuncAttributeMaxDynamicSharedMemorySize, GEMM_SMEM);
    cudaFuncSetAttribute(tc_gemm<2>, cudaFuncAttributeMaxDynamicSharedMemorySize, GEMM_SMEM);
    cudaFuncSetAttribute(tc_gemm<3>, cudaFuncAttributeMaxDynamicSharedMemorySize, GEMM_SMEM);

    // 1) split inputs
    split_f32<<<(unsigned)(((size_t)MPROJ * DD / 4 + 255) / 256), 256>>>(x, pxh, pxl, (size_t)MPROJ * DD / 4);
    split_w_t<<<dim3(DD / 32, DD / 32, 3), 256>>>(Wq, Wk, Wv, pwth, pwtl);

    // 2) fused QKV projection: [16384,1024] x [3072,1024]^T
    tc_gemm<1><<<dim3(3 * DD / GBN, MPROJ / GBM, 1), 256, GEMM_SMEM>>>(
        pxh, pxl, pwth, pwtl, nullptr,
        pqh, pql, pkh, pkl, pvh, pvl,
        MPROJ, 3 * DD, DD, DD, DD, 0, 0, 0, 1.0f, nullptr, nullptr);

    // 3) V transpose (per batch)
    transpose_v<<<dim3(SS / 32, DD / 32, BB), 256>>>(pvh, pvl, pvth, pvtl);

    // 4) QK^T + fused exp/split + row partial sums
    tc_gemm<3><<<dim3(SS / GBN, SS / GBM, BB), 256, GEMM_SMEM>>>(
        pqh, pql, pkh, pkl, nullptr,
        pph, ppl, nullptr, nullptr, nullptr, nullptr,
        SS, SS, DD, DD, DD,
        (size_t)SS * DD, (size_t)SS * DD, (size_t)SS * SS, 1.0f / 32.0f, nullptr, ppart);

    // 5) reduce partials -> rsum
    reduce_rsum<<<BB * SS / 8, 256>>>(ppart, prs);

    // 6) out = (P @ Vt^T) / rsum per batch
    tc_gemm<2><<<dim3(DD / GBN, SS / GBM, BB), 256, GEMM_SMEM>>>(
        pph, ppl, pvth, pvtl, out,
        nullptr, nullptr, nullptr, nullptr, nullptr, nullptr,
        SS, DD, SS, SS, SS,
        (size_t)SS * SS, (size_t)SS * DD, (size_t)SS * DD, 1.0f, prs, nullptr);
}

// round 8
// speedup vs baseline: 1.3079x; 1.2913x over previous
#include <cuda_runtime.h>
#include <cuda_bf16.h>
#include <cuda_fp16.h>
#include <stdint.h>
#include <math.h>

#define BB 4
#define SS 4096
#define DD 1024
#define MPROJ (BB*SS)

// ---------------- device scratch ----------------
__device__ __nv_bfloat16 g_xh[(size_t)MPROJ*DD], g_xl[(size_t)MPROJ*DD];
__device__ __nv_bfloat16 g_wth[(size_t)3*DD*DD], g_wtl[(size_t)3*DD*DD];
__device__ __half g_qh[(size_t)MPROJ*DD], g_ql[(size_t)MPROJ*DD];   // Q fp16 split
__device__ __half g_k16[(size_t)MPROJ*DD];                           // K fp16 single
__device__ __half g_v16[(size_t)MPROJ*DD];                           // V fp16 single
__device__ __half g_vt16[(size_t)MPROJ*DD];                          // V^T fp16 single
__device__ __half g_ph[(size_t)BB*SS*SS], g_pl[(size_t)BB*SS*SS];    // P fp16 split
__device__ float  g_part[(size_t)BB*SS*32];
__device__ float  g_rsum[(size_t)BB*SS];

// ---------------- PTX helpers (sm_80-level; no 'a'-suffix features) ----------------
__device__ __forceinline__ uint32_t smem_u32(const void* p) {
    uint32_t a;
    asm("{ .reg .u64 t; cvta.to.shared.u64 t, %1; cvt.u32.u64 %0, t; }" : "=r"(a) : "l"(p));
    return a;
}
__device__ __forceinline__ void cp_async16(uint32_t dst, const void* src) {
    asm volatile("cp.async.cg.shared.global [%0], [%1], 16;" :: "r"(dst), "l"(src));
}
__device__ __forceinline__ void cp_commit() {
    asm volatile("cp.async.commit_group;" ::: "memory");
}
template <int N>
__device__ __forceinline__ void cp_wait() {
    asm volatile("cp.async.wait_group %0;" :: "n"(N) : "memory");
}
__device__ __forceinline__ void ldsm_x4(uint32_t* r, uint32_t addr) {
    asm volatile("ldmatrix.sync.aligned.m8n8.x4.shared.b16 {%0,%1,%2,%3}, [%4];"
                 : "=r"(r[0]), "=r"(r[1]), "=r"(r[2]), "=r"(r[3]) : "r"(addr));
}
__device__ __forceinline__ void mma_bf16(float* c, const uint32_t* a, const uint32_t* b) {
    asm volatile(
        "mma.sync.aligned.m16n8k16.row.col.f32.bf16.bf16.f32 "
        "{%0,%1,%2,%3}, {%4,%5,%6,%7}, {%8,%9}, {%0,%1,%2,%3};"
        : "+f"(c[0]), "+f"(c[1]), "+f"(c[2]), "+f"(c[3])
        : "r"(a[0]), "r"(a[1]), "r"(a[2]), "r"(a[3]), "r"(b[0]), "r"(b[1]));
}
__device__ __forceinline__ void mma_f16(float* c, const uint32_t* a, const uint32_t* b) {
    asm volatile(
        "mma.sync.aligned.m16n8k16.row.col.f32.f16.f16.f32 "
        "{%0,%1,%2,%3}, {%4,%5,%6,%7}, {%8,%9}, {%0,%1,%2,%3};"
        : "+f"(c[0]), "+f"(c[1]), "+f"(c[2]), "+f"(c[3])
        : "r"(a[0]), "r"(a[1]), "r"(a[2]), "r"(a[3]), "r"(b[0]), "r"(b[1]));
}
// bf16 hi/lo split pack
__device__ __forceinline__ void pack_split_bf(float v0, float v1, uint32_t& hp, uint32_t& lp) {
    __nv_bfloat16 h0 = __float2bfloat16(v0);
    __nv_bfloat16 h1 = __float2bfloat16(v1);
    __nv_bfloat16 l0 = __float2bfloat16(v0 - __bfloat162float(h0));
    __nv_bfloat16 l1 = __float2bfloat16(v1 - __bfloat162float(h1));
    hp = (uint32_t)__bfloat16_as_ushort(h0) | ((uint32_t)__bfloat16_as_ushort(h1) << 16);
    lp = (uint32_t)__bfloat16_as_ushort(l0) | ((uint32_t)__bfloat16_as_ushort(l1) << 16);
}
// fp16 hi/lo split pack
__device__ __forceinline__ void pack_split_h(float v0, float v1, uint32_t& hp, uint32_t& lp) {
    __half h0 = __float2half_rn(v0);
    __half h1 = __float2half_rn(v1);
    __half l0 = __float2half_rn(v0 - __half2float(h0));
    __half l1 = __float2half_rn(v1 - __half2float(h1));
    hp = (uint32_t)__half_as_ushort(h0) | ((uint32_t)__half_as_ushort(h1) << 16);
    lp = (uint32_t)__half_as_ushort(l0) | ((uint32_t)__half_as_ushort(l1) << 16);
}
__device__ __forceinline__ uint32_t pack_h2(float v0, float v1) {
    __half h0 = __float2half_rn(v0);
    __half h1 = __float2half_rn(v1);
    return (uint32_t)__half_as_ushort(h0) | ((uint32_t)__half_as_ushort(h1) << 16);
}

// ================= common tile geometry: CTA 256x128, BK=64, warps 4x2 (64x64) ======
#define GBM 256
#define GBN 128
#define GBK 64

__device__ __forceinline__ void ld_a4(uint32_t base, uint32_t (*a)[4]) {
#pragma unroll
    for (int mt = 0; mt < 4; ++mt) ldsm_x4(a[mt], base + mt * (16 * 128));
}
__device__ __forceinline__ void ld_b8(uint32_t base, uint32_t (*b)[2]) {
    ldsm_x4(&b[0][0], base);
    ldsm_x4(&b[2][0], base + 16 * 128);
    ldsm_x4(&b[4][0], base + 32 * 128);
    ldsm_x4(&b[6][0], base + 48 * 128);
}

// ================= projection GEMM: bf16 3-pass, split x & W =================
#define AHI3 0
#define ALO3 32768
#define BHI3 65536
#define BLO3 81920
#define STAGE3B 98304
#define SMEM3 (2*STAGE3B)   // 196608

__device__ __forceinline__ void stage_in3(
    const __nv_bfloat16* Ah, const __nv_bfloat16* Al,
    const __nv_bfloat16* Bh, const __nv_bfloat16* Bl,
    int ldA, int ldB, int m0, int n0, int k0, uint32_t sb, int tid)
{
#pragma unroll
    for (int i = 0; i < 8; ++i) {
        const int idx = tid + i * 256;
        const int r = idx >> 3, c16 = idx & 7;
        const uint32_t soff = (uint32_t)(r * 128 + (((c16 ^ (r & 7)) << 4)));
        const size_t ga = (size_t)(m0 + r) * ldA + k0 + c16 * 8;
        cp_async16(sb + AHI3 + soff, Ah + ga);
        cp_async16(sb + ALO3 + soff, Al + ga);
    }
#pragma unroll
    for (int i = 0; i < 4; ++i) {
        const int idx = tid + i * 256;
        const int r = idx >> 3, c16 = idx & 7;
        const uint32_t soff = (uint32_t)(r * 128 + (((c16 ^ (r & 7)) << 4)));
        const size_t gb = (size_t)(n0 + r) * ldB + k0 + c16 * 8;
        cp_async16(sb + BHI3 + soff, Bh + gb);
        cp_async16(sb + BLO3 + soff, Bl + gb);
    }
}

__device__ __forceinline__ void mma_block_bf(float (*acc)[8][4], uint32_t (*a)[4], uint32_t (*b)[2]) {
#pragma unroll
    for (int mt = 0; mt < 4; ++mt)
#pragma unroll
        for (int nt = 0; nt < 8; ++nt) mma_bf16(acc[mt][nt], a[mt], b[nt]);
}
__device__ __forceinline__ void mma_block_h(float (*acc)[8][4], uint32_t (*a)[4], uint32_t (*b)[2]) {
#pragma unroll
    for (int mt = 0; mt < 4; ++mt)
#pragma unroll
        for (int nt = 0; nt < 8; ++nt) mma_f16(acc[mt][nt], a[mt], b[nt]);
}

// outputs: Q split fp16 (qh, ql); K single fp16; V single fp16 — routed by ncol/1024
__global__ void __launch_bounds__(256, 1)
tc_gemm_proj(const __nv_bfloat16* __restrict__ Ahi, const __nv_bfloat16* __restrict__ Alo,
             const __nv_bfloat16* __restrict__ Bhi, const __nv_bfloat16* __restrict__ Blo,
             __half* __restrict__ qh, __half* __restrict__ ql,
             __half* __restrict__ kk, __half* __restrict__ vv,
             int M, int N, int K, int ldA, int ldB)
{
    extern __shared__ __align__(128) char smem[];
    const uint32_t sbase = smem_u32(smem);
    const int tid = threadIdx.x;
    const int wid = tid >> 5, lane = tid & 31;
    const int wm = wid >> 1, wn = wid & 1;
    const int m0 = blockIdx.y * GBM, n0 = blockIdx.x * GBN;

    float acc[4][8][4];
#pragma unroll
    for (int i = 0; i < 4; ++i)
#pragma unroll
        for (int j = 0; j < 8; ++j)
#pragma unroll
            for (int q = 0; q < 4; ++q) acc[i][j][q] = 0.f;

    const int numT = K / GBK;
    stage_in3(Ahi, Alo, Bhi, Blo, ldA, ldB, m0, n0, 0, sbase, tid);
    cp_commit();

    const int a_row = wm * 64 + (lane & 15);
    const uint32_t a_rl = (uint32_t)(a_row & 7);
    const uint32_t a_hi4 = (uint32_t)(lane >> 4);
    const uint32_t a_off = (uint32_t)(a_row * 128);
    const int b_row = wn * 64 + ((lane >> 4) & 1) * 8 + (lane & 7);
    const uint32_t b_rl = (uint32_t)(b_row & 7);
    const uint32_t b_hi = (uint32_t)((lane >> 3) & 1);
    const uint32_t b_off = (uint32_t)(b_row * 128);

    for (int t = 0; t < numT; ++t) {
        if (t + 1 < numT) {
            stage_in3(Ahi, Alo, Bhi, Blo, ldA, ldB, m0, n0, (t + 1) * GBK,
                      sbase + ((t + 1) & 1) * STAGE3B, tid);
            cp_commit();
            cp_wait<1>();
        } else {
            cp_wait<0>();
        }
        __syncthreads();

        const uint32_t sbuf = sbase + (t & 1) * STAGE3B;
#pragma unroll
        for (int kc = 0; kc < 4; ++kc) {
            uint32_t af[4][4], bf[8][2], af2[4][4];
            const uint32_t a_x = ((((uint32_t)(kc * 2) + a_hi4) ^ a_rl) << 4);
            const uint32_t b_x = ((((uint32_t)(kc * 2) + b_hi) ^ b_rl) << 4);
            ld_a4(sbuf + AHI3 + a_off + a_x, af);
            ld_b8(sbuf + BHI3 + b_off + b_x, bf);
            mma_block_bf(acc, af, bf);
            ld_a4(sbuf + ALO3 + a_off + a_x, af2);
            mma_block_bf(acc, af2, bf);
            ld_b8(sbuf + BLO3 + b_off + b_x, bf);
            mma_block_bf(acc, af, bf);
        }
        __syncthreads();
    }

    const int qrow = lane >> 2;
    const int qcol = (lane & 3) * 2;
#pragma unroll
    for (int mt = 0; mt < 4; ++mt) {
        const int r0 = m0 + wm * 64 + mt * 16 + qrow;
#pragma unroll
        for (int nt = 0; nt < 8; ++nt) {
            const int ncol = n0 + wn * 64 + nt * 8 + qcol;
            const float* c = acc[mt][nt];
            const int sel = ncol >> 10;
            const int cm = ncol & (DD - 1);
            size_t off0 = (size_t)r0 * DD + cm;
            size_t off1 = off0 + (size_t)8 * DD;
            if (sel == 0) {           // Q: fp16 split
                uint32_t hp, lp;
                pack_split_h(c[0], c[1], hp, lp);
                *reinterpret_cast<uint32_t*>(qh + off0) = hp;
                *reinterpret_cast<uint32_t*>(ql + off0) = lp;
                pack_split_h(c[2], c[3], hp, lp);
                *reinterpret_cast<uint32_t*>(qh + off1) = hp;
                *reinterpret_cast<uint32_t*>(ql + off1) = lp;
            } else {                  // K or V: fp16 single
                __half* D = (sel == 1) ? kk : vv;
                *reinterpret_cast<uint32_t*>(D + off0) = pack_h2(c[0], c[1]);
                *reinterpret_cast<uint32_t*>(D + off1) = pack_h2(c[2], c[3]);
            }
        }
    }
}

// ================= fp16 2-pass GEMM: A split (hi/lo), B single ===============
#define AHI2 0
#define ALO2 32768
#define BS2  65536
#define STAGE2B 81920
#define SMEM2 (2*STAGE2B)   // 163840

__device__ __forceinline__ void stage_in2(
    const __half* Ah, const __half* Al, const __half* Bs,
    int ldA, int ldB, int m0, int n0, int k0, uint32_t sb, int tid)
{
#pragma unroll
    for (int i = 0; i < 8; ++i) {
        const int idx = tid + i * 256;
        const int r = idx >> 3, c16 = idx & 7;
        const uint32_t soff = (uint32_t)(r * 128 + (((c16 ^ (r & 7)) << 4)));
        const size_t ga = (size_t)(m0 + r) * ldA + k0 + c16 * 8;
        cp_async16(sb + AHI2 + soff, Ah + ga);
        cp_async16(sb + ALO2 + soff, Al + ga);
    }
#pragma unroll
    for (int i = 0; i < 4; ++i) {
        const int idx = tid + i * 256;
        const int r = idx >> 3, c16 = idx & 7;
        const uint32_t soff = (uint32_t)(r * 128 + (((c16 ^ (r & 7)) << 4)));
        const size_t gb = (size_t)(n0 + r) * ldB + k0 + c16 * 8;
        cp_async16(sb + BS2 + soff, Bs + gb);
    }
}

// MODE 2: C fp32 = alpha * D / rsum[row]  (PV)
// MODE 3: P = exp(alpha*D) fp16 split + per-(row,ctaX) partial sums (QK+softmax)
template <int MODE>
__global__ void __launch_bounds__(256, 1)
tc_gemm16(const __half* __restrict__ Ahi, const __half* __restrict__ Alo,
          const __half* __restrict__ Bs,
          float* __restrict__ Cf,
          __half* __restrict__ oh, __half* __restrict__ ol,
          int M, int N, int K, int ldA, int ldB,
          size_t zA, size_t zB, size_t zC,
          float alpha, const float* __restrict__ rsum, float* __restrict__ part)
{
    extern __shared__ __align__(128) char smem[];
    const uint32_t sbase = smem_u32(smem);
    const int tid = threadIdx.x;
    const int wid = tid >> 5, lane = tid & 31;
    const int wm = wid >> 1, wn = wid & 1;
    const int z = blockIdx.z;
    const int m0 = blockIdx.y * GBM, n0 = blockIdx.x * GBN;

    Ahi += (size_t)z * zA;  Alo += (size_t)z * zA;  Bs += (size_t)z * zB;

    float acc[4][8][4];
#pragma unroll
    for (int i = 0; i < 4; ++i)
#pragma unroll
        for (int j = 0; j < 8; ++j)
#pragma unroll
            for (int q = 0; q < 4; ++q) acc[i][j][q] = 0.f;

    const int numT = K / GBK;
    stage_in2(Ahi, Alo, Bs, ldA, ldB, m0, n0, 0, sbase, tid);
    cp_commit();

    const int a_row = wm * 64 + (lane & 15);
    const uint32_t a_rl = (uint32_t)(a_row & 7);
    const uint32_t a_hi4 = (uint32_t)(lane >> 4);
    const uint32_t a_off = (uint32_t)(a_row * 128);
    const int b_row = wn * 64 + ((lane >> 4) & 1) * 8 + (lane & 7);
    const uint32_t b_rl = (uint32_t)(b_row & 7);
    const uint32_t b_hi = (uint32_t)((lane >> 3) & 1);
    const uint32_t b_off = (uint32_t)(b_row * 128);

    for (int t = 0; t < numT; ++t) {
        if (t + 1 < numT) {
            stage_in2(Ahi, Alo, Bs, ldA, ldB, m0, n0, (t + 1) * GBK,
                      sbase + ((t + 1) & 1) * STAGE2B, tid);
            cp_commit();
            cp_wait<1>();
        } else {
            cp_wait<0>();
        }
        __syncthreads();

        const uint32_t sbuf = sbase + (t & 1) * STAGE2B;
#pragma unroll
        for (int kc = 0; kc < 4; ++kc) {
            uint32_t af[4][4], bf[8][2], af2[4][4];
            const uint32_t a_x = ((((uint32_t)(kc * 2) + a_hi4) ^ a_rl) << 4);
            const uint32_t b_x = ((((uint32_t)(kc * 2) + b_hi) ^ b_rl) << 4);
            ld_a4(sbuf + AHI2 + a_off + a_x, af);
            ld_b8(sbuf + BS2 + b_off + b_x, bf);
            mma_block_h(acc, af, bf);                 // hi * B
            ld_a4(sbuf + ALO2 + a_off + a_x, af2);
            mma_block_h(acc, af2, bf);                // lo * B
        }
        __syncthreads();
    }

    const int qrow = lane >> 2;
    const int qcol = (lane & 3) * 2;

    if (MODE == 3) {
        float* psum = reinterpret_cast<float*>(smem);
        float rsloc[4][2];
#pragma unroll
        for (int mt = 0; mt < 4; ++mt) { rsloc[mt][0] = 0.f; rsloc[mt][1] = 0.f; }

#pragma unroll
        for (int mt = 0; mt < 4; ++mt) {
            const int r0 = m0 + wm * 64 + mt * 16 + qrow;
#pragma unroll
            for (int nt = 0; nt < 8; ++nt) {
                const int ncol = n0 + wn * 64 + nt * 8 + qcol;
                const float* c = acc[mt][nt];
                const float e0 = __expf(alpha * c[0]);
                const float e1 = __expf(alpha * c[1]);
                const float e2 = __expf(alpha * c[2]);
                const float e3 = __expf(alpha * c[3]);
                rsloc[mt][0] += e0 + e1;
                rsloc[mt][1] += e2 + e3;
                uint32_t hp, lp;
                pack_split_h(e0, e1, hp, lp);
                size_t off = (size_t)z * zC + (size_t)r0 * N + ncol;
                *reinterpret_cast<uint32_t*>(oh + off) = hp;
                *reinterpret_cast<uint32_t*>(ol + off) = lp;
                pack_split_h(e2, e3, hp, lp);
                off += (size_t)8 * N;
                *reinterpret_cast<uint32_t*>(oh + off) = hp;
                *reinterpret_cast<uint32_t*>(ol + off) = lp;
            }
        }
#pragma unroll
        for (int mt = 0; mt < 4; ++mt)
#pragma unroll
            for (int h = 0; h < 2; ++h) {
                float v = rsloc[mt][h];
                v += __shfl_xor_sync(0xffffffffu, v, 1);
                v += __shfl_xor_sync(0xffffffffu, v, 2);
                rsloc[mt][h] = v;
            }
        if ((lane & 3) == 0) {
#pragma unroll
            for (int mt = 0; mt < 4; ++mt) {
                const int lr = wm * 64 + mt * 16 + qrow;
                psum[wn * GBM + lr] = rsloc[mt][0];
                psum[wn * GBM + lr + 8] = rsloc[mt][1];
            }
        }
        __syncthreads();
        if (tid < GBM) {
            const float s = psum[tid] + psum[GBM + tid];
            part[((size_t)z * M + m0 + tid) * gridDim.x + blockIdx.x] = s;
        }
        return;
    }

    // MODE 2
#pragma unroll
    for (int mt = 0; mt < 4; ++mt) {
        const int r0 = m0 + wm * 64 + mt * 16 + qrow;
        const float sc0 = alpha / __ldg(&rsum[(size_t)z * M + r0]);
        const float sc1 = alpha / __ldg(&rsum[(size_t)z * M + r0 + 8]);
#pragma unroll
        for (int nt = 0; nt < 8; ++nt) {
            const int ncol = n0 + wn * 64 + nt * 8 + qcol;
            const float* c = acc[mt][nt];
            float* base = Cf + (size_t)z * zC;
            float2 v0 = make_float2(sc0 * c[0], sc0 * c[1]);
            float2 v1 = make_float2(sc1 * c[2], sc1 * c[3]);
            *reinterpret_cast<float2*>(base + (size_t)r0 * N + ncol) = v0;
            *reinterpret_cast<float2*>(base + (size_t)(r0 + 8) * N + ncol) = v1;
        }
    }
}

// ---------------- aux kernels ----------------
__global__ __launch_bounds__(256)
void split_f32(const float* __restrict__ in, __nv_bfloat16* __restrict__ hi,
               __nv_bfloat16* __restrict__ lo, size_t n4)
{
    size_t i = (size_t)blockIdx.x * 256 + threadIdx.x;
    if (i >= n4) return;
    float4 v = reinterpret_cast<const float4*>(in)[i];
    uint32_t h0, l0, h1, l1;
    pack_split_bf(v.x, v.y, h0, l0);
    pack_split_bf(v.z, v.w, h1, l1);
    reinterpret_cast<uint2*>(hi)[i] = make_uint2(h0, h1);
    reinterpret_cast<uint2*>(lo)[i] = make_uint2(l0, l1);
}

__global__ __launch_bounds__(256)
void split_w_t(const float* __restrict__ Wq, const float* __restrict__ Wk,
               const float* __restrict__ Wv,
               __nv_bfloat16* __restrict__ th, __nv_bfloat16* __restrict__ tl)
{
    __shared__ float tile[32][33];
    const int zz = blockIdx.z;
    const float* W = (zz == 0) ? Wq : ((zz == 1) ? Wk : Wv);
    const int k0 = blockIdx.x * 32;
    const int n0 = blockIdx.y * 32;
    const int lx = threadIdx.x & 31, ly = threadIdx.x >> 5;
#pragma unroll
    for (int i = 0; i < 32; i += 8)
        tile[ly + i][lx] = W[(size_t)(k0 + ly + i) * DD + n0 + lx];
    __syncthreads();
#pragma unroll
    for (int i = 0; i < 32; i += 8) {
        float v = tile[lx][ly + i];
        __nv_bfloat16 h = __float2bfloat16(v);
        __nv_bfloat16 l = __float2bfloat16(v - __bfloat162float(h));
        size_t o = ((size_t)zz * DD + (n0 + ly + i)) * DD + k0 + lx;
        th[o] = h;
        tl[o] = l;
    }
}

__global__ __launch_bounds__(256)
void transpose_v16(const __half* __restrict__ v, __half* __restrict__ vt)
{
    __shared__ __half t0[32][33];
    const int b = blockIdx.z;
    const int s0 = blockIdx.x * 32, d0 = blockIdx.y * 32;
    const int lx = threadIdx.x & 31, ly = threadIdx.x >> 5;
#pragma unroll
    for (int i = 0; i < 32; i += 8)
        t0[ly + i][lx] = v[((size_t)b * SS + s0 + ly + i) * DD + d0 + lx];
    __syncthreads();
#pragma unroll
    for (int i = 0; i < 32; i += 8)
        vt[(size_t)b * SS * DD + (size_t)(d0 + ly + i) * SS + s0 + lx] = t0[lx][ly + i];
}

__global__ __launch_bounds__(256)
void reduce_rsum(const float* __restrict__ part, float* __restrict__ rsum)
{
    const int row = blockIdx.x * 8 + (threadIdx.x >> 5);
    const int lane = threadIdx.x & 31;
    float v = part[(size_t)row * 32 + lane];
#pragma unroll
    for (int o = 16; o > 0; o >>= 1) v += __shfl_xor_sync(0xffffffffu, v, o);
    if (lane == 0) rsum[row] = v;
}

// ---------------- launch ----------------
extern "C" void kernel_launch(void* const* d_in, const int* in_sizes, int n_in,
                              void* d_out, int out_size)
{
    const float* x  = (const float*)d_in[0];
    const float* Wq = (const float*)d_in[1];
    const float* Wk = (const float*)d_in[2];
    const float* Wv = (const float*)d_in[3];
    float* out = (float*)d_out;

    __nv_bfloat16 *pxh, *pxl, *pwth, *pwtl;
    __half *pqh, *pql, *pk, *pv, *pvt, *pph, *ppl;
    float *prs, *ppart;
    cudaGetSymbolAddress((void**)&pxh, g_xh);   cudaGetSymbolAddress((void**)&pxl, g_xl);
    cudaGetSymbolAddress((void**)&pwth, g_wth); cudaGetSymbolAddress((void**)&pwtl, g_wtl);
    cudaGetSymbolAddress((void**)&pqh, g_qh);   cudaGetSymbolAddress((void**)&pql, g_ql);
    cudaGetSymbolAddress((void**)&pk, g_k16);   cudaGetSymbolAddress((void**)&pv, g_v16);
    cudaGetSymbolAddress((void**)&pvt, g_vt16);
    cudaGetSymbolAddress((void**)&pph, g_ph);   cudaGetSymbolAddress((void**)&ppl, g_pl);
    cudaGetSymbolAddress((void**)&prs, g_rsum); cudaGetSymbolAddress((void**)&ppart, g_part);

    cudaFuncSetAttribute(tc_gemm_proj, cudaFuncAttributeMaxDynamicSharedMemorySize, SMEM3);
    cudaFuncSetAttribute(tc_gemm16<2>, cudaFuncAttributeMaxDynamicSharedMemorySize, SMEM2);
    cudaFuncSetAttribute(tc_gemm16<3>, cudaFuncAttributeMaxDynamicSharedMemorySize, SMEM2);

    // 1) split inputs (bf16 for accurate projections)
    split_f32<<<(unsigned)(((size_t)MPROJ * DD / 4 + 255) / 256), 256>>>(x, pxh, pxl, (size_t)MPROJ * DD / 4);
    split_w_t<<<dim3(DD / 32, DD / 32, 3), 256>>>(Wq, Wk, Wv, pwth, pwtl);

    // 2) fused QKV projection (bf16 3-pass) -> Q fp16 split, K/V fp16 single
    tc_gemm_proj<<<dim3(3 * DD / GBN, MPROJ / GBM, 1), 256, SMEM3>>>(
        pxh, pxl, pwth, pwtl, pqh, pql, pk, pv,
        MPROJ, 3 * DD, DD, DD, DD);

    // 3) V transpose (per batch)
    transpose_v16<<<dim3(SS / 32, DD / 32, BB), 256>>>(pv, pvt);

    // 4) QK^T (fp16 2-pass) + fused exp/split + row partial sums
    tc_gemm16<3><<<dim3(SS / GBN, SS / GBM, BB), 256, SMEM2>>>(
        pqh, pql, pk, nullptr, pph, ppl,
        SS, SS, DD, DD, DD,
        (size_t)SS * DD, (size_t)SS * DD, (size_t)SS * SS, 1.0f / 32.0f, nullptr, ppart);

    // 5) reduce partials -> rsum
    reduce_rsum<<<BB * SS / 8, 256>>>(ppart, prs);

    // 6) out = (P @ Vt^T) / rsum per batch (fp16 2-pass)
    tc_gemm16<2><<<dim3(DD / GBN, SS / GBM, BB), 256, SMEM2>>>(
        pph, ppl, pvt, out, nullptr, nullptr,
        SS, DD, SS, SS, SS,
        (size_t)SS * SS, (size_t)SS * DD, (size_t)SS * DD, 1.0f, prs, ppart);
}

// round 9
// speedup vs baseline: 2.5080x; 1.9176x over previous
#include <cuda_runtime.h>
#include <cuda_fp16.h>
#include <stdint.h>
#include <math.h>

#define BB 4
#define SS 4096
#define DD 1024
#define MPROJ (BB*SS)

// ---------------- device scratch ----------------
__device__ __half g_x16[(size_t)MPROJ*DD];        // x fp16
__device__ __half g_wt16[(size_t)3*DD*DD];        // [Wq^T|Wk^T|Wv^T] fp16
__device__ __half g_q16[(size_t)MPROJ*DD];
__device__ __half g_k16[(size_t)MPROJ*DD];
__device__ __half g_v16[(size_t)MPROJ*DD];
__device__ __half g_vt16[(size_t)MPROJ*DD];
__device__ __half g_p16[(size_t)BB*SS*SS];        // P fp16 (unnormalized exp)
__device__ float  g_part[(size_t)BB*SS*32];
__device__ float  g_rsum[(size_t)BB*SS];

// ---------------- PTX helpers (sm_80-level; no 'a'-suffix features) ----------------
__device__ __forceinline__ uint32_t smem_u32(const void* p) {
    uint32_t a;
    asm("{ .reg .u64 t; cvta.to.shared.u64 t, %1; cvt.u32.u64 %0, t; }" : "=r"(a) : "l"(p));
    return a;
}
__device__ __forceinline__ void cp_async16(uint32_t dst, const void* src) {
    asm volatile("cp.async.cg.shared.global [%0], [%1], 16;" :: "r"(dst), "l"(src));
}
__device__ __forceinline__ void cp_commit() {
    asm volatile("cp.async.commit_group;" ::: "memory");
}
template <int N>
__device__ __forceinline__ void cp_wait() {
    asm volatile("cp.async.wait_group %0;" :: "n"(N) : "memory");
}
__device__ __forceinline__ void ldsm_x4(uint32_t* r, uint32_t addr) {
    asm volatile("ldmatrix.sync.aligned.m8n8.x4.shared.b16 {%0,%1,%2,%3}, [%4];"
                 : "=r"(r[0]), "=r"(r[1]), "=r"(r[2]), "=r"(r[3]) : "r"(addr));
}
__device__ __forceinline__ void mma_f16(float* c, const uint32_t* a, const uint32_t* b) {
    asm volatile(
        "mma.sync.aligned.m16n8k16.row.col.f32.f16.f16.f32 "
        "{%0,%1,%2,%3}, {%4,%5,%6,%7}, {%8,%9}, {%0,%1,%2,%3};"
        : "+f"(c[0]), "+f"(c[1]), "+f"(c[2]), "+f"(c[3])
        : "r"(a[0]), "r"(a[1]), "r"(a[2]), "r"(a[3]), "r"(b[0]), "r"(b[1]));
}
__device__ __forceinline__ uint32_t pack_h2(float v0, float v1) {
    __half h0 = __float2half_rn(v0);
    __half h1 = __float2half_rn(v1);
    return (uint32_t)__half_as_ushort(h0) | ((uint32_t)__half_as_ushort(h1) << 16);
}

// ================= GEMM: CTA 256x128, BK=64, warps 4x2 (warp tile 64x64) ======
#define GBM 256
#define GBN 128
#define GBK 64
#define AOF 0
#define BOF 32768
#define STAGEB 49152          // A 32KB + B 16KB
#define GEMM_SMEM (2*STAGEB)  // 98304

__device__ __forceinline__ void stage_in(
    const __half* A, const __half* B,
    int ldA, int ldB, int m0, int n0, int k0, uint32_t sb, int tid)
{
#pragma unroll
    for (int i = 0; i < 8; ++i) {
        const int idx = tid + i * 256;
        const int r = idx >> 3, c16 = idx & 7;
        const uint32_t soff = (uint32_t)(r * 128 + (((c16 ^ (r & 7)) << 4)));
        cp_async16(sb + AOF + soff, A + (size_t)(m0 + r) * ldA + k0 + c16 * 8);
    }
#pragma unroll
    for (int i = 0; i < 4; ++i) {
        const int idx = tid + i * 256;
        const int r = idx >> 3, c16 = idx & 7;
        const uint32_t soff = (uint32_t)(r * 128 + (((c16 ^ (r & 7)) << 4)));
        cp_async16(sb + BOF + soff, B + (size_t)(n0 + r) * ldB + k0 + c16 * 8);
    }
}

__device__ __forceinline__ void ld_a4(uint32_t base, uint32_t (*a)[4]) {
#pragma unroll
    for (int mt = 0; mt < 4; ++mt) ldsm_x4(a[mt], base + mt * (16 * 128));
}
__device__ __forceinline__ void ld_b8(uint32_t base, uint32_t (*b)[2]) {
    ldsm_x4(&b[0][0], base);
    ldsm_x4(&b[2][0], base + 16 * 128);
    ldsm_x4(&b[4][0], base + 32 * 128);
    ldsm_x4(&b[6][0], base + 48 * 128);
}
__device__ __forceinline__ void mma_block(float (*acc)[8][4], uint32_t (*a)[4], uint32_t (*b)[2]) {
#pragma unroll
    for (int mt = 0; mt < 4; ++mt)
#pragma unroll
        for (int nt = 0; nt < 8; ++nt) mma_f16(acc[mt][nt], a[mt], b[nt]);
}

// MODE 1: fp16 outputs routed among q/k/v by global n / 1024 (projection)
// MODE 2: C fp32 = alpha * D / rsum[row]  (PV)
// MODE 3: P = exp(alpha*D) fp16 + per-(row,ctaX) partial sums (QK+softmax)
template <int MODE>
__global__ void __launch_bounds__(256, 1)
tc_gemm(const __half* __restrict__ A, const __half* __restrict__ B,
        float* __restrict__ Cf,
        __half* __restrict__ o0, __half* __restrict__ o1, __half* __restrict__ o2,
        int M, int N, int K, int ldA, int ldB,
        size_t zA, size_t zB, size_t zC,
        float alpha, const float* __restrict__ rsum, float* __restrict__ part)
{
    extern __shared__ __align__(128) char smem[];
    const uint32_t sbase = smem_u32(smem);
    const int tid = threadIdx.x;
    const int wid = tid >> 5, lane = tid & 31;
    const int wm = wid >> 1, wn = wid & 1;
    const int z = blockIdx.z;
    const int m0 = blockIdx.y * GBM, n0 = blockIdx.x * GBN;

    A += (size_t)z * zA;  B += (size_t)z * zB;

    float acc[4][8][4];
#pragma unroll
    for (int i = 0; i < 4; ++i)
#pragma unroll
        for (int j = 0; j < 8; ++j)
#pragma unroll
            for (int q = 0; q < 4; ++q) acc[i][j][q] = 0.f;

    const int numT = K / GBK;
    stage_in(A, B, ldA, ldB, m0, n0, 0, sbase, tid);
    cp_commit();

    const int a_row = wm * 64 + (lane & 15);
    const uint32_t a_rl = (uint32_t)(a_row & 7);
    const uint32_t a_hi4 = (uint32_t)(lane >> 4);
    const uint32_t a_off = (uint32_t)(a_row * 128);
    const int b_row = wn * 64 + ((lane >> 4) & 1) * 8 + (lane & 7);
    const uint32_t b_rl = (uint32_t)(b_row & 7);
    const uint32_t b_hi = (uint32_t)((lane >> 3) & 1);
    const uint32_t b_off = (uint32_t)(b_row * 128);

    for (int t = 0; t < numT; ++t) {
        if (t + 1 < numT) {
            stage_in(A, B, ldA, ldB, m0, n0, (t + 1) * GBK,
                     sbase + ((t + 1) & 1) * STAGEB, tid);
            cp_commit();
            cp_wait<1>();
        } else {
            cp_wait<0>();
        }
        __syncthreads();

        const uint32_t sbuf = sbase + (t & 1) * STAGEB;
#pragma unroll
        for (int kc = 0; kc < 4; ++kc) {
            uint32_t af[4][4], bf[8][2];
            const uint32_t a_x = ((((uint32_t)(kc * 2) + a_hi4) ^ a_rl) << 4);
            const uint32_t b_x = ((((uint32_t)(kc * 2) + b_hi) ^ b_rl) << 4);
            ld_a4(sbuf + AOF + a_off + a_x, af);
            ld_b8(sbuf + BOF + b_off + b_x, bf);
            mma_block(acc, af, bf);
        }
        __syncthreads();
    }

    const int qrow = lane >> 2;
    const int qcol = (lane & 3) * 2;

    if (MODE == 3) {
        float* psum = reinterpret_cast<float*>(smem);
        float rsloc[4][2];
#pragma unroll
        for (int mt = 0; mt < 4; ++mt) { rsloc[mt][0] = 0.f; rsloc[mt][1] = 0.f; }

#pragma unroll
        for (int mt = 0; mt < 4; ++mt) {
            const int r0 = m0 + wm * 64 + mt * 16 + qrow;
#pragma unroll
            for (int nt = 0; nt < 8; ++nt) {
                const int ncol = n0 + wn * 64 + nt * 8 + qcol;
                const float* c = acc[mt][nt];
                const float e0 = __expf(alpha * c[0]);
                const float e1 = __expf(alpha * c[1]);
                const float e2 = __expf(alpha * c[2]);
                const float e3 = __expf(alpha * c[3]);
                rsloc[mt][0] += e0 + e1;
                rsloc[mt][1] += e2 + e3;
                size_t off = (size_t)z * zC + (size_t)r0 * N + ncol;
                *reinterpret_cast<uint32_t*>(o0 + off) = pack_h2(e0, e1);
                *reinterpret_cast<uint32_t*>(o0 + off + (size_t)8 * N) = pack_h2(e2, e3);
            }
        }
#pragma unroll
        for (int mt = 0; mt < 4; ++mt)
#pragma unroll
            for (int h = 0; h < 2; ++h) {
                float v = rsloc[mt][h];
                v += __shfl_xor_sync(0xffffffffu, v, 1);
                v += __shfl_xor_sync(0xffffffffu, v, 2);
                rsloc[mt][h] = v;
            }
        if ((lane & 3) == 0) {
#pragma unroll
            for (int mt = 0; mt < 4; ++mt) {
                const int lr = wm * 64 + mt * 16 + qrow;
                psum[wn * GBM + lr] = rsloc[mt][0];
                psum[wn * GBM + lr + 8] = rsloc[mt][1];
            }
        }
        __syncthreads();
        if (tid < GBM) {
            const float s = psum[tid] + psum[GBM + tid];
            part[((size_t)z * M + m0 + tid) * gridDim.x + blockIdx.x] = s;
        }
        return;
    }

#pragma unroll
    for (int mt = 0; mt < 4; ++mt) {
        const int r0 = m0 + wm * 64 + mt * 16 + qrow;
        float sc0 = alpha, sc1 = alpha;
        if (MODE == 2) {
            sc0 = alpha / __ldg(&rsum[(size_t)z * M + r0]);
            sc1 = alpha / __ldg(&rsum[(size_t)z * M + r0 + 8]);
        }
#pragma unroll
        for (int nt = 0; nt < 8; ++nt) {
            const int ncol = n0 + wn * 64 + nt * 8 + qcol;
            const float* c = acc[mt][nt];
            if (MODE == 2) {
                float* base = Cf + (size_t)z * zC;
                float2 v0 = make_float2(sc0 * c[0], sc0 * c[1]);
                float2 v1 = make_float2(sc1 * c[2], sc1 * c[3]);
                *reinterpret_cast<float2*>(base + (size_t)r0 * N + ncol) = v0;
                *reinterpret_cast<float2*>(base + (size_t)(r0 + 8) * N + ncol) = v1;
            } else {   // MODE 1
                const int sel = ncol >> 10;
                __half* D = (sel == 0) ? o0 : ((sel == 1) ? o1 : o2);
                const int cm = ncol & (DD - 1);
                size_t off = (size_t)r0 * DD + cm;
                *reinterpret_cast<uint32_t*>(D + off) = pack_h2(c[0], c[1]);
                *reinterpret_cast<uint32_t*>(D + off + (size_t)8 * DD) = pack_h2(c[2], c[3]);
            }
        }
    }
}

// ---------------- aux kernels ----------------
__global__ __launch_bounds__(256)
void conv_x(const float* __restrict__ in, __half* __restrict__ o, size_t n4)
{
    size_t i = (size_t)blockIdx.x * 256 + threadIdx.x;
    if (i >= n4) return;
    float4 v = reinterpret_cast<const float4*>(in)[i];
    reinterpret_cast<uint2*>(o)[i] = make_uint2(pack_h2(v.x, v.y), pack_h2(v.z, v.w));
}

__global__ __launch_bounds__(256)
void conv_w_t(const float* __restrict__ Wq, const float* __restrict__ Wk,
              const float* __restrict__ Wv, __half* __restrict__ wt)
{
    __shared__ float tile[32][33];
    const int zz = blockIdx.z;
    const float* W = (zz == 0) ? Wq : ((zz == 1) ? Wk : Wv);
    const int k0 = blockIdx.x * 32;
    const int n0 = blockIdx.y * 32;
    const int lx = threadIdx.x & 31, ly = threadIdx.x >> 5;
#pragma unroll
    for (int i = 0; i < 32; i += 8)
        tile[ly + i][lx] = W[(size_t)(k0 + ly + i) * DD + n0 + lx];
    __syncthreads();
#pragma unroll
    for (int i = 0; i < 32; i += 8) {
        size_t o = ((size_t)zz * DD + (n0 + ly + i)) * DD + k0 + lx;
        wt[o] = __float2half_rn(tile[lx][ly + i]);
    }
}

__global__ __launch_bounds__(256)
void transpose_v16(const __half* __restrict__ v, __half* __restrict__ vt)
{
    __shared__ __half t0[32][33];
    const int b = blockIdx.z;
    const int s0 = blockIdx.x * 32, d0 = blockIdx.y * 32;
    const int lx = threadIdx.x & 31, ly = threadIdx.x >> 5;
#pragma unroll
    for (int i = 0; i < 32; i += 8)
        t0[ly + i][lx] = v[((size_t)b * SS + s0 + ly + i) * DD + d0 + lx];
    __syncthreads();
#pragma unroll
    for (int i = 0; i < 32; i += 8)
        vt[(size_t)b * SS * DD + (size_t)(d0 + ly + i) * SS + s0 + lx] = t0[lx][ly + i];
}

__global__ __launch_bounds__(256)
void reduce_rsum(const float* __restrict__ part, float* __restrict__ rsum)
{
    const int row = blockIdx.x * 8 + (threadIdx.x >> 5);
    const int lane = threadIdx.x & 31;
    float v = part[(size_t)row * 32 + lane];
#pragma unroll
    for (int o = 16; o > 0; o >>= 1) v += __shfl_xor_sync(0xffffffffu, v, o);
    if (lane == 0) rsum[row] = v;
}

// ---------------- launch ----------------
extern "C" void kernel_launch(void* const* d_in, const int* in_sizes, int n_in,
                              void* d_out, int out_size)
{
    const float* x  = (const float*)d_in[0];
    const float* Wq = (const float*)d_in[1];
    const float* Wk = (const float*)d_in[2];
    const float* Wv = (const float*)d_in[3];
    float* out = (float*)d_out;

    __half *px, *pwt, *pq, *pk, *pv, *pvt, *pp;
    float *prs, *ppart;
    cudaGetSymbolAddress((void**)&px, g_x16);   cudaGetSymbolAddress((void**)&pwt, g_wt16);
    cudaGetSymbolAddress((void**)&pq, g_q16);   cudaGetSymbolAddress((void**)&pk, g_k16);
    cudaGetSymbolAddress((void**)&pv, g_v16);   cudaGetSymbolAddress((void**)&pvt, g_vt16);
    cudaGetSymbolAddress((void**)&pp, g_p16);
    cudaGetSymbolAddress((void**)&prs, g_rsum); cudaGetSymbolAddress((void**)&ppart, g_part);

    cudaFuncSetAttribute(tc_gemm<1>, cudaFuncAttributeMaxDynamicSharedMemorySize, GEMM_SMEM);
    cudaFuncSetAttribute(tc_gemm<2>, cudaFuncAttributeMaxDynamicSharedMemorySize, GEMM_SMEM);
    cudaFuncSetAttribute(tc_gemm<3>, cudaFuncAttributeMaxDynamicSharedMemorySize, GEMM_SMEM);

    // 1) convert inputs to fp16
    conv_x<<<(unsigned)(((size_t)MPROJ * DD / 4 + 255) / 256), 256>>>(x, px, (size_t)MPROJ * DD / 4);
    conv_w_t<<<dim3(DD / 32, DD / 32, 3), 256>>>(Wq, Wk, Wv, pwt);

    // 2) fused QKV projection: [16384,1024] x [3072,1024]^T -> Q,K,V fp16
    tc_gemm<1><<<dim3(3 * DD / GBN, MPROJ / GBM, 1), 256, GEMM_SMEM>>>(
        px, pwt, nullptr, pq, pk, pv,
        MPROJ, 3 * DD, DD, DD, DD, 0, 0, 0, 1.0f, nullptr, nullptr);

    // 3) V transpose (per batch)
    transpose_v16<<<dim3(SS / 32, DD / 32, BB), 256>>>(pv, pvt);

    // 4) QK^T + fused exp + row partial sums
    tc_gemm<3><<<dim3(SS / GBN, SS / GBM, BB), 256, GEMM_SMEM>>>(
        pq, pk, nullptr, pp, nullptr, nullptr,
        SS, SS, DD, DD, DD,
        (size_t)SS * DD, (size_t)SS * DD, (size_t)SS * SS, 1.0f / 32.0f, nullptr, ppart);

    // 5) reduce partials -> rsum
    reduce_rsum<<<BB * SS / 8, 256>>>(ppart, prs);

    // 6) out = (P @ Vt^T) / rsum per batch
    tc_gemm<2><<<dim3(DD / GBN, SS / GBM, BB), 256, GEMM_SMEM>>>(
        pp, pvt, out, nullptr, nullptr, nullptr,
        SS, DD, SS, SS, SS,
        (size_t)SS * SS, (size_t)SS * DD, (size_t)SS * DD, 1.0f, prs, ppart);
}

// round 10
// speedup vs baseline: 2.6314x; 1.0492x over previous
#include <cuda_runtime.h>
#include <cuda_fp16.h>
#include <stdint.h>
#include <math.h>

#define BB 4
#define SS 4096
#define DD 1024
#define MPROJ (BB*SS)

// ---------------- device scratch ----------------
__device__ __half g_x16[(size_t)MPROJ*DD];
__device__ __half g_wt16[(size_t)3*DD*DD];
__device__ __half g_q16[(size_t)MPROJ*DD];
__device__ __half g_k16[(size_t)MPROJ*DD];
__device__ __half g_v16[(size_t)MPROJ*DD];
__device__ __half g_vt16[(size_t)MPROJ*DD];
__device__ __half g_p16[(size_t)BB*SS*SS];
__device__ float  g_part[(size_t)BB*SS*32];
__device__ float  g_rsum[(size_t)BB*SS];

// ---------------- PTX helpers (sm_80-level; no 'a'-suffix features) ----------------
__device__ __forceinline__ uint32_t smem_u32(const void* p) {
    uint32_t a;
    asm("{ .reg .u64 t; cvta.to.shared.u64 t, %1; cvt.u32.u64 %0, t; }" : "=r"(a) : "l"(p));
    return a;
}
__device__ __forceinline__ void cp_async16(uint32_t dst, const void* src) {
    asm volatile("cp.async.cg.shared.global [%0], [%1], 16;" :: "r"(dst), "l"(src));
}
__device__ __forceinline__ void cp_commit() {
    asm volatile("cp.async.commit_group;" ::: "memory");
}
template <int N>
__device__ __forceinline__ void cp_wait() {
    asm volatile("cp.async.wait_group %0;" :: "n"(N) : "memory");
}
__device__ __forceinline__ void ldsm_x4(uint32_t* r, uint32_t addr) {
    asm volatile("ldmatrix.sync.aligned.m8n8.x4.shared.b16 {%0,%1,%2,%3}, [%4];"
                 : "=r"(r[0]), "=r"(r[1]), "=r"(r[2]), "=r"(r[3]) : "r"(addr));
}
__device__ __forceinline__ void mma_f16(float* c, const uint32_t* a, const uint32_t* b) {
    asm volatile(
        "mma.sync.aligned.m16n8k16.row.col.f32.f16.f16.f32 "
        "{%0,%1,%2,%3}, {%4,%5,%6,%7}, {%8,%9}, {%0,%1,%2,%3};"
        : "+f"(c[0]), "+f"(c[1]), "+f"(c[2]), "+f"(c[3])
        : "r"(a[0]), "r"(a[1]), "r"(a[2]), "r"(a[3]), "r"(b[0]), "r"(b[1]));
}
__device__ __forceinline__ uint32_t pack_h2(float v0, float v1) {
    __half h0 = __float2half_rn(v0);
    __half h1 = __float2half_rn(v1);
    return (uint32_t)__half_as_ushort(h0) | ((uint32_t)__half_as_ushort(h1) << 16);
}

// ===== GEMM: CTA 256x128, BK=128, 2 stages (96KB each), warps 4x2 (64x64) =====
#define GBM 256
#define GBN 128
#define GBK 128
#define ROWB 256               // bytes per smem row (128 fp16)
#define AOF 0
#define ABYTES (256*ROWB)      // 65536
#define BOF ABYTES
#define STAGEB (ABYTES + 128*ROWB)   // 98304
#define GEMM_SMEM (2*STAGEB)         // 196608

__device__ __forceinline__ void stage_in(
    const __half* A, const __half* B,
    int ldA, int ldB, int m0, int n0, int k0, uint32_t sb, int tid)
{
    // A: 256 rows x 16 chunks of 16B
#pragma unroll
    for (int i = 0; i < 16; ++i) {
        const int idx = tid + i * 256;
        const int r = idx >> 4, c16 = idx & 15;
        const uint32_t soff = (uint32_t)(r * ROWB + (((c16 ^ (r & 7)) << 4)));
        cp_async16(sb + AOF + soff, A + (size_t)(m0 + r) * ldA + k0 + c16 * 8);
    }
    // B: 128 rows x 16 chunks
#pragma unroll
    for (int i = 0; i < 8; ++i) {
        const int idx = tid + i * 256;
        const int r = idx >> 4, c16 = idx & 15;
        const uint32_t soff = (uint32_t)(r * ROWB + (((c16 ^ (r & 7)) << 4)));
        cp_async16(sb + BOF + soff, B + (size_t)(n0 + r) * ldB + k0 + c16 * 8);
    }
}

__device__ __forceinline__ void ld_a4(uint32_t base, uint32_t (*a)[4]) {
#pragma unroll
    for (int mt = 0; mt < 4; ++mt) ldsm_x4(a[mt], base + mt * (16 * ROWB));
}
__device__ __forceinline__ void ld_b8(uint32_t base, uint32_t (*b)[2]) {
    ldsm_x4(&b[0][0], base);
    ldsm_x4(&b[2][0], base + 16 * ROWB);
    ldsm_x4(&b[4][0], base + 32 * ROWB);
    ldsm_x4(&b[6][0], base + 48 * ROWB);
}
__device__ __forceinline__ void mma_block(float (*acc)[8][4], uint32_t (*a)[4], uint32_t (*b)[2]) {
#pragma unroll
    for (int mt = 0; mt < 4; ++mt)
#pragma unroll
        for (int nt = 0; nt < 8; ++nt) mma_f16(acc[mt][nt], a[mt], b[nt]);
}

// MODE 1: fp16 outputs routed among q/k/v by global n / 1024 (projection)
// MODE 2: C fp32 = alpha * D / rsum[row]  (PV)
// MODE 3: P = exp(alpha*D) fp16 + per-(row,ctaX) partial sums (QK+softmax)
template <int MODE>
__global__ void __launch_bounds__(256, 1)
tc_gemm(const __half* __restrict__ A, const __half* __restrict__ B,
        float* __restrict__ Cf,
        __half* __restrict__ o0, __half* __restrict__ o1, __half* __restrict__ o2,
        int M, int N, int K, int ldA, int ldB,
        size_t zA, size_t zB, size_t zC,
        float alpha, const float* __restrict__ rsum, float* __restrict__ part)
{
    extern __shared__ __align__(128) char smem[];
    const uint32_t sbase = smem_u32(smem);
    const int tid = threadIdx.x;
    const int wid = tid >> 5, lane = tid & 31;
    const int wm = wid >> 1, wn = wid & 1;
    const int z = blockIdx.z;
    const int m0 = blockIdx.y * GBM, n0 = blockIdx.x * GBN;

    A += (size_t)z * zA;  B += (size_t)z * zB;

    float acc[4][8][4];
#pragma unroll
    for (int i = 0; i < 4; ++i)
#pragma unroll
        for (int j = 0; j < 8; ++j)
#pragma unroll
            for (int q = 0; q < 4; ++q) acc[i][j][q] = 0.f;

    const int numT = K / GBK;
    stage_in(A, B, ldA, ldB, m0, n0, 0, sbase, tid);
    cp_commit();

    const int a_row = wm * 64 + (lane & 15);
    const uint32_t a_rl = (uint32_t)(a_row & 7);
    const uint32_t a_hi4 = (uint32_t)(lane >> 4);
    const uint32_t a_off = (uint32_t)(a_row * ROWB);
    const int b_row = wn * 64 + ((lane >> 4) & 1) * 8 + (lane & 7);
    const uint32_t b_rl = (uint32_t)(b_row & 7);
    const uint32_t b_hi = (uint32_t)((lane >> 3) & 1);
    const uint32_t b_off = (uint32_t)(b_row * ROWB);

    for (int t = 0; t < numT; ++t) {
        if (t + 1 < numT) {
            stage_in(A, B, ldA, ldB, m0, n0, (t + 1) * GBK,
                     sbase + ((t + 1) & 1) * STAGEB, tid);
            cp_commit();
            cp_wait<1>();
        } else {
            cp_wait<0>();
        }
        __syncthreads();

        const uint32_t sbuf = sbase + (t & 1) * STAGEB;
#pragma unroll
        for (int kc = 0; kc < 8; ++kc) {
            uint32_t af[4][4], bf[8][2];
            const uint32_t a_x = ((((uint32_t)(kc * 2) + a_hi4) ^ a_rl) << 4);
            const uint32_t b_x = ((((uint32_t)(kc * 2) + b_hi) ^ b_rl) << 4);
            ld_a4(sbuf + AOF + a_off + a_x, af);
            ld_b8(sbuf + BOF + b_off + b_x, bf);
            mma_block(acc, af, bf);
        }
        __syncthreads();
    }

    const int qrow = lane >> 2;
    const int qcol = (lane & 3) * 2;

    if (MODE == 3) {
        float* psum = reinterpret_cast<float*>(smem);
        float rsloc[4][2];
#pragma unroll
        for (int mt = 0; mt < 4; ++mt) { rsloc[mt][0] = 0.f; rsloc[mt][1] = 0.f; }

#pragma unroll
        for (int mt = 0; mt < 4; ++mt) {
            const int r0 = m0 + wm * 64 + mt * 16 + qrow;
#pragma unroll
            for (int nt = 0; nt < 8; ++nt) {
                const int ncol = n0 + wn * 64 + nt * 8 + qcol;
                const float* c = acc[mt][nt];
                const float e0 = __expf(alpha * c[0]);
                const float e1 = __expf(alpha * c[1]);
                const float e2 = __expf(alpha * c[2]);
                const float e3 = __expf(alpha * c[3]);
                rsloc[mt][0] += e0 + e1;
                rsloc[mt][1] += e2 + e3;
                size_t off = (size_t)z * zC + (size_t)r0 * N + ncol;
                *reinterpret_cast<uint32_t*>(o0 + off) = pack_h2(e0, e1);
                *reinterpret_cast<uint32_t*>(o0 + off + (size_t)8 * N) = pack_h2(e2, e3);
            }
        }
#pragma unroll
        for (int mt = 0; mt < 4; ++mt)
#pragma unroll
            for (int h = 0; h < 2; ++h) {
                float v = rsloc[mt][h];
                v += __shfl_xor_sync(0xffffffffu, v, 1);
                v += __shfl_xor_sync(0xffffffffu, v, 2);
                rsloc[mt][h] = v;
            }
        if ((lane & 3) == 0) {
#pragma unroll
            for (int mt = 0; mt < 4; ++mt) {
                const int lr = wm * 64 + mt * 16 + qrow;
                psum[wn * GBM + lr] = rsloc[mt][0];
                psum[wn * GBM + lr + 8] = rsloc[mt][1];
            }
        }
        __syncthreads();
        if (tid < GBM) {
            const float s = psum[tid] + psum[GBM + tid];
            part[((size_t)z * M + m0 + tid) * gridDim.x + blockIdx.x] = s;
        }
        return;
    }

#pragma unroll
    for (int mt = 0; mt < 4; ++mt) {
        const int r0 = m0 + wm * 64 + mt * 16 + qrow;
        float sc0 = alpha, sc1 = alpha;
        if (MODE == 2) {
            sc0 = alpha / __ldg(&rsum[(size_t)z * M + r0]);
            sc1 = alpha / __ldg(&rsum[(size_t)z * M + r0 + 8]);
        }
#pragma unroll
        for (int nt = 0; nt < 8; ++nt) {
            const int ncol = n0 + wn * 64 + nt * 8 + qcol;
            const float* c = acc[mt][nt];
            if (MODE == 2) {
                float* base = Cf + (size_t)z * zC;
                float2 v0 = make_float2(sc0 * c[0], sc0 * c[1]);
                float2 v1 = make_float2(sc1 * c[2], sc1 * c[3]);
                *reinterpret_cast<float2*>(base + (size_t)r0 * N + ncol) = v0;
                *reinterpret_cast<float2*>(base + (size_t)(r0 + 8) * N + ncol) = v1;
            } else {   // MODE 1
                const int sel = ncol >> 10;
                __half* D = (sel == 0) ? o0 : ((sel == 1) ? o1 : o2);
                const int cm = ncol & (DD - 1);
                size_t off = (size_t)r0 * DD + cm;
                *reinterpret_cast<uint32_t*>(D + off) = pack_h2(c[0], c[1]);
                *reinterpret_cast<uint32_t*>(D + off + (size_t)8 * DD) = pack_h2(c[2], c[3]);
            }
        }
    }
}

// ---------------- aux kernels ----------------
__global__ __launch_bounds__(256)
void conv_x(const float* __restrict__ in, __half* __restrict__ o, size_t n4)
{
    size_t i = (size_t)blockIdx.x * 256 + threadIdx.x;
    if (i >= n4) return;
    float4 v = reinterpret_cast<const float4*>(in)[i];
    reinterpret_cast<uint2*>(o)[i] = make_uint2(pack_h2(v.x, v.y), pack_h2(v.z, v.w));
}

__global__ __launch_bounds__(256)
void conv_w_t(const float* __restrict__ Wq, const float* __restrict__ Wk,
              const float* __restrict__ Wv, __half* __restrict__ wt)
{
    __shared__ float tile[32][33];
    const int zz = blockIdx.z;
    const float* W = (zz == 0) ? Wq : ((zz == 1) ? Wk : Wv);
    const int k0 = blockIdx.x * 32;
    const int n0 = blockIdx.y * 32;
    const int lx = threadIdx.x & 31, ly = threadIdx.x >> 5;
#pragma unroll
    for (int i = 0; i < 32; i += 8)
        tile[ly + i][lx] = W[(size_t)(k0 + ly + i) * DD + n0 + lx];
    __syncthreads();
#pragma unroll
    for (int i = 0; i < 32; i += 8) {
        size_t o = ((size_t)zz * DD + (n0 + ly + i)) * DD + k0 + lx;
        wt[o] = __float2half_rn(tile[lx][ly + i]);
    }
}

__global__ __launch_bounds__(256)
void transpose_v16(const __half* __restrict__ v, __half* __restrict__ vt)
{
    __shared__ __half t0[32][33];
    const int b = blockIdx.z;
    const int s0 = blockIdx.x * 32, d0 = blockIdx.y * 32;
    const int lx = threadIdx.x & 31, ly = threadIdx.x >> 5;
#pragma unroll
    for (int i = 0; i < 32; i += 8)
        t0[ly + i][lx] = v[((size_t)b * SS + s0 + ly + i) * DD + d0 + lx];
    __syncthreads();
#pragma unroll
    for (int i = 0; i < 32; i += 8)
        vt[(size_t)b * SS * DD + (size_t)(d0 + ly + i) * SS + s0 + lx] = t0[lx][ly + i];
}

__global__ __launch_bounds__(256)
void reduce_rsum(const float* __restrict__ part, float* __restrict__ rsum)
{
    const int row = blockIdx.x * 8 + (threadIdx.x >> 5);
    const int lane = threadIdx.x & 31;
    float v = part[(size_t)row * 32 + lane];
#pragma unroll
    for (int o = 16; o > 0; o >>= 1) v += __shfl_xor_sync(0xffffffffu, v, o);
    if (lane == 0) rsum[row] = v;
}

// ---------------- launch ----------------
extern "C" void kernel_launch(void* const* d_in, const int* in_sizes, int n_in,
                              void* d_out, int out_size)
{
    const float* x  = (const float*)d_in[0];
    const float* Wq = (const float*)d_in[1];
    const float* Wk = (const float*)d_in[2];
    const float* Wv = (const float*)d_in[3];
    float* out = (float*)d_out;

    __half *px, *pwt, *pq, *pk, *pv, *pvt, *pp;
    float *prs, *ppart;
    cudaGetSymbolAddress((void**)&px, g_x16);   cudaGetSymbolAddress((void**)&pwt, g_wt16);
    cudaGetSymbolAddress((void**)&pq, g_q16);   cudaGetSymbolAddress((void**)&pk, g_k16);
    cudaGetSymbolAddress((void**)&pv, g_v16);   cudaGetSymbolAddress((void**)&pvt, g_vt16);
    cudaGetSymbolAddress((void**)&pp, g_p16);
    cudaGetSymbolAddress((void**)&prs, g_rsum); cudaGetSymbolAddress((void**)&ppart, g_part);

    cudaFuncSetAttribute(tc_gemm<1>, cudaFuncAttributeMaxDynamicSharedMemorySize, GEMM_SMEM);
    cudaFuncSetAttribute(tc_gemm<2>, cudaFuncAttributeMaxDynamicSharedMemorySize, GEMM_SMEM);
    cudaFuncSetAttribute(tc_gemm<3>, cudaFuncAttributeMaxDynamicSharedMemorySize, GEMM_SMEM);

    // 1) convert inputs to fp16
    conv_x<<<(unsigned)(((size_t)MPROJ * DD / 4 + 255) / 256), 256>>>(x, px, (size_t)MPROJ * DD / 4);
    conv_w_t<<<dim3(DD / 32, DD / 32, 3), 256>>>(Wq, Wk, Wv, pwt);

    // 2) fused QKV projection: [16384,1024] x [3072,1024]^T -> Q,K,V fp16
    tc_gemm<1><<<dim3(3 * DD / GBN, MPROJ / GBM, 1), 256, GEMM_SMEM>>>(
        px, pwt, nullptr, pq, pk, pv,
        MPROJ, 3 * DD, DD, DD, DD, 0, 0, 0, 1.0f, nullptr, nullptr);

    // 3) V transpose (per batch)
    transpose_v16<<<dim3(SS / 32, DD / 32, BB), 256>>>(pv, pvt);

    // 4) QK^T + fused exp + row partial sums
    tc_gemm<3><<<dim3(SS / GBN, SS / GBM, BB), 256, GEMM_SMEM>>>(
        pq, pk, nullptr, pp, nullptr, nullptr,
        SS, SS, DD, DD, DD,
        (size_t)SS * DD, (size_t)SS * DD, (size_t)SS * SS, 1.0f / 32.0f, nullptr, ppart);

    // 5) reduce partials -> rsum
    reduce_rsum<<<BB * SS / 8, 256>>>(ppart, prs);

    // 6) out = (P @ Vt^T) / rsum per batch
    tc_gemm<2><<<dim3(DD / GBN, SS / GBM, BB), 256, GEMM_SMEM>>>(
        pp, pvt, out, nullptr, nullptr, nullptr,
        SS, DD, SS, SS, SS,
        (size_t)SS * SS, (size_t)SS * DD, (size_t)SS * DD, 1.0f, prs, ppart);
}

// round 11
// speedup vs baseline: 2.6399x; 1.0032x over previous
#include <cuda_runtime.h>
#include <cuda_fp16.h>
#include <stdint.h>
#include <math.h>

#define BB 4
#define SS 4096
#define DD 1024
#define MPROJ (BB*SS)

// ---------------- device scratch ----------------
__device__ __half g_x16[(size_t)MPROJ*DD];
__device__ __half g_wt16[(size_t)3*DD*DD];
__device__ __half g_q16[(size_t)MPROJ*DD];
__device__ __half g_k16[(size_t)MPROJ*DD];
__device__ __half g_v16[(size_t)MPROJ*DD];
__device__ __half g_vt16[(size_t)MPROJ*DD];
__device__ __half g_p16[(size_t)BB*SS*SS];
__device__ float  g_part[(size_t)BB*SS*32];
__device__ float  g_rsum[(size_t)BB*SS];

// ---------------- PTX helpers (sm_80-level; no 'a'-suffix features) ----------------
__device__ __forceinline__ uint32_t smem_u32(const void* p) {
    uint32_t a;
    asm("{ .reg .u64 t; cvta.to.shared.u64 t, %1; cvt.u32.u64 %0, t; }" : "=r"(a) : "l"(p));
    return a;
}
__device__ __forceinline__ void cp_async16(uint32_t dst, const void* src) {
    asm volatile("cp.async.cg.shared.global [%0], [%1], 16;" :: "r"(dst), "l"(src));
}
__device__ __forceinline__ void cp_commit() {
    asm volatile("cp.async.commit_group;" ::: "memory");
}
template <int N>
__device__ __forceinline__ void cp_wait() {
    asm volatile("cp.async.wait_group %0;" :: "n"(N) : "memory");
}
__device__ __forceinline__ void ldsm_x4(uint32_t* r, uint32_t addr) {
    asm volatile("ldmatrix.sync.aligned.m8n8.x4.shared.b16 {%0,%1,%2,%3}, [%4];"
                 : "=r"(r[0]), "=r"(r[1]), "=r"(r[2]), "=r"(r[3]) : "r"(addr));
}
__device__ __forceinline__ void mma_f16(float* c, const uint32_t* a, const uint32_t* b) {
    asm volatile(
        "mma.sync.aligned.m16n8k16.row.col.f32.f16.f16.f32 "
        "{%0,%1,%2,%3}, {%4,%5,%6,%7}, {%8,%9}, {%0,%1,%2,%3};"
        : "+f"(c[0]), "+f"(c[1]), "+f"(c[2]), "+f"(c[3])
        : "r"(a[0]), "r"(a[1]), "r"(a[2]), "r"(a[3]), "r"(b[0]), "r"(b[1]));
}
__device__ __forceinline__ uint32_t pack_h2(float v0, float v1) {
    __half h0 = __float2half_rn(v0);
    __half h1 = __float2half_rn(v1);
    return (uint32_t)__half_as_ushort(h0) | ((uint32_t)__half_as_ushort(h1) << 16);
}

// ===== GEMM: CTA (64*MT)x128, BK=128, 2 stages, 8 warps (4 x 2), warp (16*MT)x64 ====
#define GBN 128
#define GBK 128
#define ROWB 256               // bytes per smem row (128 fp16)

template <int MT> struct Geom {
    static constexpr int GBM = 64 * MT;
    static constexpr int ABYTES = GBM * ROWB;
    static constexpr int BOF = ABYTES;
    static constexpr int STAGEB = ABYTES + GBN * ROWB;
    static constexpr int SMEM = 2 * STAGEB;
};

template <int MT>
__device__ __forceinline__ void stage_in(
    const __half* A, const __half* B,
    int ldA, int ldB, int m0, int n0, int k0, uint32_t sb, int tid)
{
#pragma unroll
    for (int i = 0; i < MT * 4; ++i) {        // A: GBM rows x 16 chunks of 16B
        const int idx = tid + i * 256;
        const int r = idx >> 4, c16 = idx & 15;
        const uint32_t soff = (uint32_t)(r * ROWB + (((c16 ^ (r & 7)) << 4)));
        cp_async16(sb + soff, A + (size_t)(m0 + r) * ldA + k0 + c16 * 8);
    }
#pragma unroll
    for (int i = 0; i < 8; ++i) {             // B: 128 rows x 16 chunks
        const int idx = tid + i * 256;
        const int r = idx >> 4, c16 = idx & 15;
        const uint32_t soff = (uint32_t)(r * ROWB + (((c16 ^ (r & 7)) << 4)));
        cp_async16(sb + Geom<MT>::BOF + soff, B + (size_t)(n0 + r) * ldB + k0 + c16 * 8);
    }
}

template <int MT>
__device__ __forceinline__ void ld_a(uint32_t base, uint32_t (*a)[4]) {
#pragma unroll
    for (int mt = 0; mt < MT; ++mt) ldsm_x4(a[mt], base + mt * (16 * ROWB));
}
__device__ __forceinline__ void ld_b8(uint32_t base, uint32_t (*b)[2]) {
    ldsm_x4(&b[0][0], base);
    ldsm_x4(&b[2][0], base + 16 * ROWB);
    ldsm_x4(&b[4][0], base + 32 * ROWB);
    ldsm_x4(&b[6][0], base + 48 * ROWB);
}
template <int MT>
__device__ __forceinline__ void mma_block(float (*acc)[8][4], uint32_t (*a)[4], uint32_t (*b)[2]) {
#pragma unroll
    for (int mt = 0; mt < MT; ++mt)
#pragma unroll
        for (int nt = 0; nt < 8; ++nt) mma_f16(acc[mt][nt], a[mt], b[nt]);
}

// MODE 1: fp16 outputs routed among q/k/v by global n / 1024 (projection)
// MODE 2: C fp32 = alpha * D / rsum[row]  (PV)
// MODE 3: P = exp(alpha*D) fp16 + per-(row,ctaX) partial sums (QK+softmax)
template <int MODE, int MT>
__global__ void __launch_bounds__(256, 1)
tc_gemm(const __half* __restrict__ A, const __half* __restrict__ B,
        float* __restrict__ Cf,
        __half* __restrict__ o0, __half* __restrict__ o1, __half* __restrict__ o2,
        int M, int N, int K, int ldA, int ldB,
        size_t zA, size_t zB, size_t zC,
        float alpha, const float* __restrict__ rsum, float* __restrict__ part)
{
    constexpr int GBM = Geom<MT>::GBM;
    constexpr int STAGEB = Geom<MT>::STAGEB;

    extern __shared__ __align__(128) char smem[];
    const uint32_t sbase = smem_u32(smem);
    const int tid = threadIdx.x;
    const int wid = tid >> 5, lane = tid & 31;
    const int wm = wid >> 1, wn = wid & 1;
    const int z = blockIdx.z;
    const int m0 = blockIdx.y * GBM, n0 = blockIdx.x * GBN;

    A += (size_t)z * zA;  B += (size_t)z * zB;

    float acc[MT][8][4];
#pragma unroll
    for (int i = 0; i < MT; ++i)
#pragma unroll
        for (int j = 0; j < 8; ++j)
#pragma unroll
            for (int q = 0; q < 4; ++q) acc[i][j][q] = 0.f;

    const int numT = K / GBK;
    stage_in<MT>(A, B, ldA, ldB, m0, n0, 0, sbase, tid);
    cp_commit();

    const int a_row = wm * (16 * MT) + (lane & 15);
    const uint32_t a_rl = (uint32_t)(a_row & 7);
    const uint32_t a_hi4 = (uint32_t)(lane >> 4);
    const uint32_t a_off = (uint32_t)(a_row * ROWB);
    const int b_row = wn * 64 + ((lane >> 4) & 1) * 8 + (lane & 7);
    const uint32_t b_rl = (uint32_t)(b_row & 7);
    const uint32_t b_hi = (uint32_t)((lane >> 3) & 1);
    const uint32_t b_off = (uint32_t)(b_row * ROWB);

    for (int t = 0; t < numT; ++t) {
        if (t + 1 < numT) {
            stage_in<MT>(A, B, ldA, ldB, m0, n0, (t + 1) * GBK,
                         sbase + ((t + 1) & 1) * STAGEB, tid);
            cp_commit();
            cp_wait<1>();
        } else {
            cp_wait<0>();
        }
        __syncthreads();

        const uint32_t sbuf = sbase + (t & 1) * STAGEB;
#pragma unroll
        for (int kc = 0; kc < 8; ++kc) {
            uint32_t af[MT][4], bf[8][2];
            const uint32_t a_x = ((((uint32_t)(kc * 2) + a_hi4) ^ a_rl) << 4);
            const uint32_t b_x = ((((uint32_t)(kc * 2) + b_hi) ^ b_rl) << 4);
            ld_a<MT>(sbuf + a_off + a_x, af);
            ld_b8(sbuf + Geom<MT>::BOF + b_off + b_x, bf);
            mma_block<MT>(acc, af, bf);
        }
        __syncthreads();
    }

    const int qrow = lane >> 2;
    const int qcol = (lane & 3) * 2;

    if (MODE == 3) {
        float* psum = reinterpret_cast<float*>(smem);
        float rsloc[MT][2];
#pragma unroll
        for (int mt = 0; mt < MT; ++mt) { rsloc[mt][0] = 0.f; rsloc[mt][1] = 0.f; }

#pragma unroll
        for (int mt = 0; mt < MT; ++mt) {
            const int r0 = m0 + wm * (16 * MT) + mt * 16 + qrow;
#pragma unroll
            for (int nt = 0; nt < 8; ++nt) {
                const int ncol = n0 + wn * 64 + nt * 8 + qcol;
                const float* c = acc[mt][nt];
                const float e0 = __expf(alpha * c[0]);
                const float e1 = __expf(alpha * c[1]);
                const float e2 = __expf(alpha * c[2]);
                const float e3 = __expf(alpha * c[3]);
                rsloc[mt][0] += e0 + e1;
                rsloc[mt][1] += e2 + e3;
                size_t off = (size_t)z * zC + (size_t)r0 * N + ncol;
                *reinterpret_cast<uint32_t*>(o0 + off) = pack_h2(e0, e1);
                *reinterpret_cast<uint32_t*>(o0 + off + (size_t)8 * N) = pack_h2(e2, e3);
            }
        }
#pragma unroll
        for (int mt = 0; mt < MT; ++mt)
#pragma unroll
            for (int h = 0; h < 2; ++h) {
                float v = rsloc[mt][h];
                v += __shfl_xor_sync(0xffffffffu, v, 1);
                v += __shfl_xor_sync(0xffffffffu, v, 2);
                rsloc[mt][h] = v;
            }
        if ((lane & 3) == 0) {
#pragma unroll
            for (int mt = 0; mt < MT; ++mt) {
                const int lr = wm * (16 * MT) + mt * 16 + qrow;
                psum[wn * GBM + lr] = rsloc[mt][0];
                psum[wn * GBM + lr + 8] = rsloc[mt][1];
            }
        }
        __syncthreads();
        if (tid < GBM) {
            const float s = psum[tid] + psum[GBM + tid];
            part[((size_t)z * M + m0 + tid) * gridDim.x + blockIdx.x] = s;
        }
        return;
    }

#pragma unroll
    for (int mt = 0; mt < MT; ++mt) {
        const int r0 = m0 + wm * (16 * MT) + mt * 16 + qrow;
        float sc0 = alpha, sc1 = alpha;
        if (MODE == 2) {
            sc0 = alpha / __ldg(&rsum[(size_t)z * M + r0]);
            sc1 = alpha / __ldg(&rsum[(size_t)z * M + r0 + 8]);
        }
#pragma unroll
        for (int nt = 0; nt < 8; ++nt) {
            const int ncol = n0 + wn * 64 + nt * 8 + qcol;
            const float* c = acc[mt][nt];
            if (MODE == 2) {
                float* base = Cf + (size_t)z * zC;
                float2 v0 = make_float2(sc0 * c[0], sc0 * c[1]);
                float2 v1 = make_float2(sc1 * c[2], sc1 * c[3]);
                *reinterpret_cast<float2*>(base + (size_t)r0 * N + ncol) = v0;
                *reinterpret_cast<float2*>(base + (size_t)(r0 + 8) * N + ncol) = v1;
            } else {   // MODE 1
                const int sel = ncol >> 10;
                __half* D = (sel == 0) ? o0 : ((sel == 1) ? o1 : o2);
                const int cm = ncol & (DD - 1);
                size_t off = (size_t)r0 * DD + cm;
                *reinterpret_cast<uint32_t*>(D + off) = pack_h2(c[0], c[1]);
                *reinterpret_cast<uint32_t*>(D + off + (size_t)8 * DD) = pack_h2(c[2], c[3]);
            }
        }
    }
}

// ---------------- aux kernels ----------------
__global__ __launch_bounds__(256)
void conv_x(const float* __restrict__ in, __half* __restrict__ o, size_t n4)
{
    size_t i = (size_t)blockIdx.x * 256 + threadIdx.x;
    if (i >= n4) return;
    float4 v = reinterpret_cast<const float4*>(in)[i];
    reinterpret_cast<uint2*>(o)[i] = make_uint2(pack_h2(v.x, v.y), pack_h2(v.z, v.w));
}

__global__ __launch_bounds__(256)
void conv_w_t(const float* __restrict__ Wq, const float* __restrict__ Wk,
              const float* __restrict__ Wv, __half* __restrict__ wt)
{
    __shared__ float tile[32][33];
    const int zz = blockIdx.z;
    const float* W = (zz == 0) ? Wq : ((zz == 1) ? Wk : Wv);
    const int k0 = blockIdx.x * 32;
    const int n0 = blockIdx.y * 32;
    const int lx = threadIdx.x & 31, ly = threadIdx.x >> 5;
#pragma unroll
    for (int i = 0; i < 32; i += 8)
        tile[ly + i][lx] = W[(size_t)(k0 + ly + i) * DD + n0 + lx];
    __syncthreads();
#pragma unroll
    for (int i = 0; i < 32; i += 8) {
        size_t o = ((size_t)zz * DD + (n0 + ly + i)) * DD + k0 + lx;
        wt[o] = __float2half_rn(tile[lx][ly + i]);
    }
}

__global__ __launch_bounds__(256)
void transpose_v16(const __half* __restrict__ v, __half* __restrict__ vt)
{
    __shared__ __half t0[32][33];
    const int b = blockIdx.z;
    const int s0 = blockIdx.x * 32, d0 = blockIdx.y * 32;
    const int lx = threadIdx.x & 31, ly = threadIdx.x >> 5;
#pragma unroll
    for (int i = 0; i < 32; i += 8)
        t0[ly + i][lx] = v[((size_t)b * SS + s0 + ly + i) * DD + d0 + lx];
    __syncthreads();
#pragma unroll
    for (int i = 0; i < 32; i += 8)
        vt[(size_t)b * SS * DD + (size_t)(d0 + ly + i) * SS + s0 + lx] = t0[lx][ly + i];
}

__global__ __launch_bounds__(256)
void reduce_rsum(const float* __restrict__ part, float* __restrict__ rsum)
{
    const int row = blockIdx.x * 8 + (threadIdx.x >> 5);
    const int lane = threadIdx.x & 31;
    float v = part[(size_t)row * 32 + lane];
#pragma unroll
    for (int o = 16; o > 0; o >>= 1) v += __shfl_xor_sync(0xffffffffu, v, o);
    if (lane == 0) rsum[row] = v;
}

// ---------------- launch ----------------
extern "C" void kernel_launch(void* const* d_in, const int* in_sizes, int n_in,
                              void* d_out, int out_size)
{
    const float* x  = (const float*)d_in[0];
    const float* Wq = (const float*)d_in[1];
    const float* Wk = (const float*)d_in[2];
    const float* Wv = (const float*)d_in[3];
    float* out = (float*)d_out;

    __half *px, *pwt, *pq, *pk, *pv, *pvt, *pp;
    float *prs, *ppart;
    cudaGetSymbolAddress((void**)&px, g_x16);   cudaGetSymbolAddress((void**)&pwt, g_wt16);
    cudaGetSymbolAddress((void**)&pq, g_q16);   cudaGetSymbolAddress((void**)&pk, g_k16);
    cudaGetSymbolAddress((void**)&pv, g_v16);   cudaGetSymbolAddress((void**)&pvt, g_vt16);
    cudaGetSymbolAddress((void**)&pp, g_p16);
    cudaGetSymbolAddress((void**)&prs, g_rsum); cudaGetSymbolAddress((void**)&ppart, g_part);

    cudaFuncSetAttribute(tc_gemm<1,4>, cudaFuncAttributeMaxDynamicSharedMemorySize, Geom<4>::SMEM);
    cudaFuncSetAttribute(tc_gemm<3,4>, cudaFuncAttributeMaxDynamicSharedMemorySize, Geom<4>::SMEM);
    cudaFuncSetAttribute(tc_gemm<2,2>, cudaFuncAttributeMaxDynamicSharedMemorySize, Geom<2>::SMEM);

    // 1) convert inputs to fp16
    conv_x<<<(unsigned)(((size_t)MPROJ * DD / 4 + 255) / 256), 256>>>(x, px, (size_t)MPROJ * DD / 4);
    conv_w_t<<<dim3(DD / 32, DD / 32, 3), 256>>>(Wq, Wk, Wv, pwt);

    // 2) fused QKV projection: [16384,1024] x [3072,1024]^T -> Q,K,V fp16 (256-row tile)
    tc_gemm<1,4><<<dim3(3 * DD / GBN, MPROJ / 256, 1), 256, Geom<4>::SMEM>>>(
        px, pwt, nullptr, pq, pk, pv,
        MPROJ, 3 * DD, DD, DD, DD, 0, 0, 0, 1.0f, nullptr, nullptr);

    // 3) V transpose (per batch)
    transpose_v16<<<dim3(SS / 32, DD / 32, BB), 256>>>(pv, pvt);

    // 4) QK^T + fused exp + row partial sums (256-row tile)
    tc_gemm<3,4><<<dim3(SS / GBN, SS / 256, BB), 256, Geom<4>::SMEM>>>(
        pq, pk, nullptr, pp, nullptr, nullptr,
        SS, SS, DD, DD, DD,
        (size_t)SS * DD, (size_t)SS * DD, (size_t)SS * SS, 1.0f / 32.0f, nullptr, ppart);

    // 5) reduce partials -> rsum
    reduce_rsum<<<BB * SS / 8, 256>>>(ppart, prs);

    // 6) out = (P @ Vt^T) / rsum per batch (128-row tile -> 1024 CTAs, kills wave tail)
    tc_gemm<2,2><<<dim3(DD / GBN, SS / 128, BB), 256, Geom<2>::SMEM>>>(
        pp, pvt, out, nullptr, nullptr, nullptr,
        SS, DD, SS, SS, SS,
        (size_t)SS * SS, (size_t)SS * DD, (size_t)SS * DD, 1.0f, prs, ppart);
}

// round 12
// speedup vs baseline: 2.6581x; 1.0069x over previous
#include <cuda_runtime.h>
#include <cuda_fp16.h>
#include <stdint.h>
#include <math.h>

#define BB 4
#define SS 4096
#define DD 1024
#define MPROJ (BB*SS)

// ---------------- device scratch ----------------
__device__ __half g_x16[(size_t)MPROJ*DD];
__device__ __half g_w16[(size_t)DD*3*DD];        // [K=1024, N=3072] = [Wq|Wk|Wv] cols
__device__ __half g_q16[(size_t)MPROJ*DD];
__device__ __half g_k16[(size_t)MPROJ*DD];
__device__ __half g_v16[(size_t)MPROJ*DD];
__device__ __half g_p16[(size_t)BB*SS*SS];
__device__ float  g_part[(size_t)BB*SS*32];
__device__ float  g_rsum[(size_t)BB*SS];

// ---------------- PTX helpers (sm_80-level; no 'a'-suffix features) ----------------
__device__ __forceinline__ uint32_t smem_u32(const void* p) {
    uint32_t a;
    asm("{ .reg .u64 t; cvta.to.shared.u64 t, %1; cvt.u32.u64 %0, t; }" : "=r"(a) : "l"(p));
    return a;
}
__device__ __forceinline__ void cp_async16(uint32_t dst, const void* src) {
    asm volatile("cp.async.cg.shared.global [%0], [%1], 16;" :: "r"(dst), "l"(src));
}
__device__ __forceinline__ void cp_commit() {
    asm volatile("cp.async.commit_group;" ::: "memory");
}
template <int N>
__device__ __forceinline__ void cp_wait() {
    asm volatile("cp.async.wait_group %0;" :: "n"(N) : "memory");
}
__device__ __forceinline__ void ldsm_x4(uint32_t* r, uint32_t addr) {
    asm volatile("ldmatrix.sync.aligned.m8n8.x4.shared.b16 {%0,%1,%2,%3}, [%4];"
                 : "=r"(r[0]), "=r"(r[1]), "=r"(r[2]), "=r"(r[3]) : "r"(addr));
}
__device__ __forceinline__ void ldsm_x4_t(uint32_t* r, uint32_t addr) {
    asm volatile("ldmatrix.sync.aligned.m8n8.x4.trans.shared.b16 {%0,%1,%2,%3}, [%4];"
                 : "=r"(r[0]), "=r"(r[1]), "=r"(r[2]), "=r"(r[3]) : "r"(addr));
}
__device__ __forceinline__ void mma_f16(float* c, const uint32_t* a, const uint32_t* b) {
    asm volatile(
        "mma.sync.aligned.m16n8k16.row.col.f32.f16.f16.f32 "
        "{%0,%1,%2,%3}, {%4,%5,%6,%7}, {%8,%9}, {%0,%1,%2,%3};"
        : "+f"(c[0]), "+f"(c[1]), "+f"(c[2]), "+f"(c[3])
        : "r"(a[0]), "r"(a[1]), "r"(a[2]), "r"(a[3]), "r"(b[0]), "r"(b[1]));
}
__device__ __forceinline__ uint32_t pack_h2(float v0, float v1) {
    __half h0 = __float2half_rn(v0);
    __half h1 = __float2half_rn(v1);
    return (uint32_t)__half_as_ushort(h0) | ((uint32_t)__half_as_ushort(h1) << 16);
}

// ===== GEMM: CTA (64*MT)x128, BK=128, 2 stages, 8 warps (MTx?); warp (16*MT)x64 ====
// TRB=true : B is [N,K] row-major (NT), plain ldsm on n-rows
// TRB=false: B is [K,N] row-major (NN), ldsm.trans on k-rows
#define GBN 128
#define GBK 128
#define ROWB 256               // bytes per smem row (128 fp16)

template <int MT> struct Geom {
    static constexpr int GBM = 64 * MT;
    static constexpr int ABYTES = GBM * ROWB;
    static constexpr int BOF = ABYTES;
    static constexpr int STAGEB = ABYTES + 128 * ROWB;   // B tile always 128 rows
    static constexpr int SMEM = 2 * STAGEB;
};

template <int MT, bool TRB>
__device__ __forceinline__ void stage_in(
    const __half* A, const __half* B,
    int ldA, int ldB, int m0, int n0, int k0, uint32_t sb, int tid)
{
#pragma unroll
    for (int i = 0; i < MT * 4; ++i) {        // A: GBM rows x 16 chunks of 16B
        const int idx = tid + i * 256;
        const int r = idx >> 4, c16 = idx & 15;
        const uint32_t soff = (uint32_t)(r * ROWB + (((c16 ^ (r & 7)) << 4)));
        cp_async16(sb + soff, A + (size_t)(m0 + r) * ldA + k0 + c16 * 8);
    }
#pragma unroll
    for (int i = 0; i < 8; ++i) {             // B: 128 rows x 16 chunks
        const int idx = tid + i * 256;
        const int r = idx >> 4, c16 = idx & 15;
        const uint32_t soff = (uint32_t)(r * ROWB + (((c16 ^ (r & 7)) << 4)));
        const __half* src = TRB ? (B + (size_t)(n0 + r) * ldB + k0 + c16 * 8)
                                : (B + (size_t)(k0 + r) * ldB + n0 + c16 * 8);
        cp_async16(sb + Geom<MT>::BOF + soff, src);
    }
}

template <int MT>
__device__ __forceinline__ void ld_a(uint32_t base, uint32_t (*a)[4]) {
#pragma unroll
    for (int mt = 0; mt < MT; ++mt) ldsm_x4(a[mt], base + mt * (16 * ROWB));
}
template <int MT>
__device__ __forceinline__ void mma_block(float (*acc)[8][4], uint32_t (*a)[4], uint32_t (*b)[2]) {
#pragma unroll
    for (int mt = 0; mt < MT; ++mt)
#pragma unroll
        for (int nt = 0; nt < 8; ++nt) mma_f16(acc[mt][nt], a[mt], b[nt]);
}

// MODE 1: fp16 outputs routed among q/k/v by global n / 1024 (projection)
// MODE 2: C fp32 = alpha * D / rsum[row]  (PV)
// MODE 3: P = exp(alpha*D) fp16 + per-(row,ctaX) partial sums (QK+softmax)
template <int MODE, int MT, bool TRB>
__global__ void __launch_bounds__(256, 1)
tc_gemm(const __half* __restrict__ A, const __half* __restrict__ B,
        float* __restrict__ Cf,
        __half* __restrict__ o0, __half* __restrict__ o1, __half* __restrict__ o2,
        int M, int N, int K, int ldA, int ldB,
        size_t zA, size_t zB, size_t zC,
        float alpha, const float* __restrict__ rsum, float* __restrict__ part)
{
    constexpr int GBM = Geom<MT>::GBM;
    constexpr int STAGEB = Geom<MT>::STAGEB;
    constexpr int BOF = Geom<MT>::BOF;

    extern __shared__ __align__(128) char smem[];
    const uint32_t sbase = smem_u32(smem);
    const int tid = threadIdx.x;
    const int wid = tid >> 5, lane = tid & 31;
    const int wm = wid >> 1, wn = wid & 1;
    const int z = blockIdx.z;
    const int m0 = blockIdx.y * GBM, n0 = blockIdx.x * GBN;

    A += (size_t)z * zA;  B += (size_t)z * zB;

    float acc[MT][8][4];
#pragma unroll
    for (int i = 0; i < MT; ++i)
#pragma unroll
        for (int j = 0; j < 8; ++j)
#pragma unroll
            for (int q = 0; q < 4; ++q) acc[i][j][q] = 0.f;

    const int numT = K / GBK;
    stage_in<MT, TRB>(A, B, ldA, ldB, m0, n0, 0, sbase, tid);
    cp_commit();

    // A fragment addressing (row-major NT, plain ldsm)
    const int a_row = wm * (16 * MT) + (lane & 15);
    const uint32_t a_rl = (uint32_t)(a_row & 7);
    const uint32_t a_hi4 = (uint32_t)(lane >> 4);
    const uint32_t a_off = (uint32_t)(a_row * ROWB);

    // B fragment addressing — NT path
    const int b_row = wn * 64 + ((lane >> 4) & 1) * 8 + (lane & 7);
    const uint32_t b_rl = (uint32_t)(b_row & 7);
    const uint32_t b_hi = (uint32_t)((lane >> 3) & 1);
    const uint32_t b_off = (uint32_t)(b_row * ROWB);

    // B fragment addressing — NN (trans) path
    const uint32_t t_klocal = (uint32_t)(((lane >> 3) & 1) * 8 + (lane & 7));
    const uint32_t t_rl = (uint32_t)(lane & 7);
    const uint32_t t_hi = (uint32_t)(lane >> 4);        // 0/1 -> n +8 cols (1 c16)

    for (int t = 0; t < numT; ++t) {
        if (t + 1 < numT) {
            stage_in<MT, TRB>(A, B, ldA, ldB, m0, n0, (t + 1) * GBK,
                              sbase + ((t + 1) & 1) * STAGEB, tid);
            cp_commit();
            cp_wait<1>();
        } else {
            cp_wait<0>();
        }
        __syncthreads();

        const uint32_t sbuf = sbase + (t & 1) * STAGEB;
#pragma unroll
        for (int kc = 0; kc < 8; ++kc) {
            uint32_t af[MT][4], bf[8][2];
            const uint32_t a_x = ((((uint32_t)(kc * 2) + a_hi4) ^ a_rl) << 4);
            ld_a<MT>(sbuf + a_off + a_x, af);

            if (TRB) {
                const uint32_t b_x = ((((uint32_t)(kc * 2) + b_hi) ^ b_rl) << 4);
                const uint32_t bb = sbuf + BOF + b_off + b_x;
                ldsm_x4(&bf[0][0], bb);
                ldsm_x4(&bf[2][0], bb + 16 * ROWB);
                ldsm_x4(&bf[4][0], bb + 32 * ROWB);
                ldsm_x4(&bf[6][0], bb + 48 * ROWB);
            } else {
                const uint32_t row_off = ((uint32_t)(kc * 16) + t_klocal) * ROWB;
                const uint32_t bb = sbuf + BOF + row_off;
#pragma unroll
                for (int nt = 0; nt < 4; ++nt) {
                    const uint32_t c16 = (uint32_t)(wn * 8 + nt * 2) + t_hi;
                    ldsm_x4_t(&bf[nt * 2][0], bb + ((c16 ^ t_rl) << 4));
                }
            }
            mma_block<MT>(acc, af, bf);
        }
        __syncthreads();
    }

    const int qrow = lane >> 2;
    const int qcol = (lane & 3) * 2;

    if (MODE == 3) {
        float* psum = reinterpret_cast<float*>(smem);
        float rsloc[MT][2];
#pragma unroll
        for (int mt = 0; mt < MT; ++mt) { rsloc[mt][0] = 0.f; rsloc[mt][1] = 0.f; }

#pragma unroll
        for (int mt = 0; mt < MT; ++mt) {
            const int r0 = m0 + wm * (16 * MT) + mt * 16 + qrow;
#pragma unroll
            for (int nt = 0; nt < 8; ++nt) {
                const int ncol = n0 + wn * 64 + nt * 8 + qcol;
                const float* c = acc[mt][nt];
                const float e0 = __expf(alpha * c[0]);
                const float e1 = __expf(alpha * c[1]);
                const float e2 = __expf(alpha * c[2]);
                const float e3 = __expf(alpha * c[3]);
                rsloc[mt][0] += e0 + e1;
                rsloc[mt][1] += e2 + e3;
                size_t off = (size_t)z * zC + (size_t)r0 * N + ncol;
                *reinterpret_cast<uint32_t*>(o0 + off) = pack_h2(e0, e1);
                *reinterpret_cast<uint32_t*>(o0 + off + (size_t)8 * N) = pack_h2(e2, e3);
            }
        }
#pragma unroll
        for (int mt = 0; mt < MT; ++mt)
#pragma unroll
            for (int h = 0; h < 2; ++h) {
                float v = rsloc[mt][h];
                v += __shfl_xor_sync(0xffffffffu, v, 1);
                v += __shfl_xor_sync(0xffffffffu, v, 2);
                rsloc[mt][h] = v;
            }
        if ((lane & 3) == 0) {
#pragma unroll
            for (int mt = 0; mt < MT; ++mt) {
                const int lr = wm * (16 * MT) + mt * 16 + qrow;
                psum[wn * GBM + lr] = rsloc[mt][0];
                psum[wn * GBM + lr + 8] = rsloc[mt][1];
            }
        }
        __syncthreads();
        if (tid < GBM) {
            const float s = psum[tid] + psum[GBM + tid];
            part[((size_t)z * M + m0 + tid) * gridDim.x + blockIdx.x] = s;
        }
        return;
    }

#pragma unroll
    for (int mt = 0; mt < MT; ++mt) {
        const int r0 = m0 + wm * (16 * MT) + mt * 16 + qrow;
        float sc0 = alpha, sc1 = alpha;
        if (MODE == 2) {
            sc0 = alpha / __ldg(&rsum[(size_t)z * M + r0]);
            sc1 = alpha / __ldg(&rsum[(size_t)z * M + r0 + 8]);
        }
#pragma unroll
        for (int nt = 0; nt < 8; ++nt) {
            const int ncol = n0 + wn * 64 + nt * 8 + qcol;
            const float* c = acc[mt][nt];
            if (MODE == 2) {
                float* base = Cf + (size_t)z * zC;
                float2 v0 = make_float2(sc0 * c[0], sc0 * c[1]);
                float2 v1 = make_float2(sc1 * c[2], sc1 * c[3]);
                *reinterpret_cast<float2*>(base + (size_t)r0 * N + ncol) = v0;
                *reinterpret_cast<float2*>(base + (size_t)(r0 + 8) * N + ncol) = v1;
            } else {   // MODE 1
                const int sel = ncol >> 10;
                __half* D = (sel == 0) ? o0 : ((sel == 1) ? o1 : o2);
                const int cm = ncol & (DD - 1);
                size_t off = (size_t)r0 * DD + cm;
                *reinterpret_cast<uint32_t*>(D + off) = pack_h2(c[0], c[1]);
                *reinterpret_cast<uint32_t*>(D + off + (size_t)8 * DD) = pack_h2(c[2], c[3]);
            }
        }
    }
}

// ---------------- aux kernels ----------------
__global__ __launch_bounds__(256)
void conv_x(const float* __restrict__ in, __half* __restrict__ o, size_t n4)
{
    size_t i = (size_t)blockIdx.x * 256 + threadIdx.x;
    if (i >= n4) return;
    float4 v = reinterpret_cast<const float4*>(in)[i];
    reinterpret_cast<uint2*>(o)[i] = make_uint2(pack_h2(v.x, v.y), pack_h2(v.z, v.w));
}

// convert W [D,D] fp32 -> fused [K=1024, N=3072] fp16 (no transpose)
__global__ __launch_bounds__(256)
void conv_w(const float* __restrict__ Wq, const float* __restrict__ Wk,
            const float* __restrict__ Wv, __half* __restrict__ wt)
{
    const int zz = blockIdx.y;
    const float* W = (zz == 0) ? Wq : ((zz == 1) ? Wk : Wv);
    size_t i = (size_t)blockIdx.x * 256 + threadIdx.x;    // over DD*DD/4
    if (i >= (size_t)DD * DD / 4) return;
    const int k = (int)(i / (DD / 4));
    const int nq = (int)(i % (DD / 4));
    float4 v = reinterpret_cast<const float4*>(W)[i];
    uint2 pk = make_uint2(pack_h2(v.x, v.y), pack_h2(v.z, v.w));
    *reinterpret_cast<uint2*>(wt + (size_t)k * (3 * DD) + zz * DD + nq * 4) = pk;
}

__global__ __launch_bounds__(256)
void reduce_rsum(const float* __restrict__ part, float* __restrict__ rsum)
{
    const int row = blockIdx.x * 8 + (threadIdx.x >> 5);
    const int lane = threadIdx.x & 31;
    float v = part[(size_t)row * 32 + lane];
#pragma unroll
    for (int o = 16; o > 0; o >>= 1) v += __shfl_xor_sync(0xffffffffu, v, o);
    if (lane == 0) rsum[row] = v;
}

// ---------------- launch ----------------
extern "C" void kernel_launch(void* const* d_in, const int* in_sizes, int n_in,
                              void* d_out, int out_size)
{
    const float* x  = (const float*)d_in[0];
    const float* Wq = (const float*)d_in[1];
    const float* Wk = (const float*)d_in[2];
    const float* Wv = (const float*)d_in[3];
    float* out = (float*)d_out;

    __half *px, *pw, *pq, *pk, *pv, *pp;
    float *prs, *ppart;
    cudaGetSymbolAddress((void**)&px, g_x16);   cudaGetSymbolAddress((void**)&pw, g_w16);
    cudaGetSymbolAddress((void**)&pq, g_q16);   cudaGetSymbolAddress((void**)&pk, g_k16);
    cudaGetSymbolAddress((void**)&pv, g_v16);   cudaGetSymbolAddress((void**)&pp, g_p16);
    cudaGetSymbolAddress((void**)&prs, g_rsum); cudaGetSymbolAddress((void**)&ppart, g_part);

    cudaFuncSetAttribute((const void*)tc_gemm<1,4,false>, cudaFuncAttributeMaxDynamicSharedMemorySize, Geom<4>::SMEM);
    cudaFuncSetAttribute((const void*)tc_gemm<3,4,true>,  cudaFuncAttributeMaxDynamicSharedMemorySize, Geom<4>::SMEM);
    cudaFuncSetAttribute((const void*)tc_gemm<2,2,false>, cudaFuncAttributeMaxDynamicSharedMemorySize, Geom<2>::SMEM);

    // 1) convert inputs to fp16 (W without transpose: [K, 3N] fused)
    conv_x<<<(unsigned)(((size_t)MPROJ * DD / 4 + 255) / 256), 256>>>(x, px, (size_t)MPROJ * DD / 4);
    conv_w<<<dim3((unsigned)(((size_t)DD * DD / 4 + 255) / 256), 3), 256>>>(Wq, Wk, Wv, pw);

    // 2) fused QKV projection (NN: B = W [1024, 3072]) -> Q,K,V fp16
    tc_gemm<1,4,false><<<dim3(3 * DD / GBN, MPROJ / 256, 1), 256, Geom<4>::SMEM>>>(
        px, pw, nullptr, pq, pk, pv,
        MPROJ, 3 * DD, DD, DD, 3 * DD, 0, 0, 0, 1.0f, nullptr, nullptr);

    // 3) QK^T (NT) + fused exp + row partial sums
    tc_gemm<3,4,true><<<dim3(SS / GBN, SS / 256, BB), 256, Geom<4>::SMEM>>>(
        pq, pk, nullptr, pp, nullptr, nullptr,
        SS, SS, DD, DD, DD,
        (size_t)SS * DD, (size_t)SS * DD, (size_t)SS * SS, 1.0f / 32.0f, nullptr, ppart);

    // 4) reduce partials -> rsum
    reduce_rsum<<<BB * SS / 8, 256>>>(ppart, prs);

    // 5) out = (P @ V) / rsum per batch (NN: B = V [S, D], no transpose needed)
    tc_gemm<2,2,false><<<dim3(DD / GBN, SS / 128, BB), 256, Geom<2>::SMEM>>>(
        pp, pv, out, nullptr, nullptr, nullptr,
        SS, DD, SS, SS, DD,
        (size_t)SS * SS, (size_t)SS * DD, (size_t)SS * DD, 1.0f, prs, ppart);
}

// round 13
// speedup vs baseline: 2.9249x; 1.1004x over previous
#include <cuda_runtime.h>
#include <cuda_fp16.h>
#include <stdint.h>
#include <math.h>

#define BB 4
#define SS 4096
#define DD 1024
#define MPROJ (BB*SS)

// ---------------- device scratch ----------------
__device__ __half g_x16[(size_t)MPROJ*DD];
__device__ __half g_w16[(size_t)DD*3*DD];        // [K=1024, N=3072] = [Wq|Wk|Wv] cols
__device__ __half g_q16[(size_t)MPROJ*DD];
__device__ __half g_k16[(size_t)MPROJ*DD];
__device__ __half g_v16[(size_t)MPROJ*DD];
__device__ __half g_p16[(size_t)BB*SS*SS];
__device__ float  g_part[(size_t)BB*SS*32];
__device__ float  g_rsum[(size_t)BB*SS];

// ---------------- PTX helpers (sm_80-level; no 'a'-suffix features) ----------------
__device__ __forceinline__ uint32_t smem_u32(const void* p) {
    uint32_t a;
    asm("{ .reg .u64 t; cvta.to.shared.u64 t, %1; cvt.u32.u64 %0, t; }" : "=r"(a) : "l"(p));
    return a;
}
__device__ __forceinline__ void cp_async16(uint32_t dst, const void* src) {
    asm volatile("cp.async.cg.shared.global [%0], [%1], 16;" :: "r"(dst), "l"(src));
}
__device__ __forceinline__ void cp_commit() {
    asm volatile("cp.async.commit_group;" ::: "memory");
}
template <int N>
__device__ __forceinline__ void cp_wait() {
    asm volatile("cp.async.wait_group %0;" :: "n"(N) : "memory");
}
__device__ __forceinline__ void ldsm_x4(uint32_t* r, uint32_t addr) {
    asm volatile("ldmatrix.sync.aligned.m8n8.x4.shared.b16 {%0,%1,%2,%3}, [%4];"
                 : "=r"(r[0]), "=r"(r[1]), "=r"(r[2]), "=r"(r[3]) : "r"(addr));
}
__device__ __forceinline__ void ldsm_x4_t(uint32_t* r, uint32_t addr) {
    asm volatile("ldmatrix.sync.aligned.m8n8.x4.trans.shared.b16 {%0,%1,%2,%3}, [%4];"
                 : "=r"(r[0]), "=r"(r[1]), "=r"(r[2]), "=r"(r[3]) : "r"(addr));
}
__device__ __forceinline__ void mma_f16(float* c, const uint32_t* a, const uint32_t* b) {
    asm volatile(
        "mma.sync.aligned.m16n8k16.row.col.f32.f16.f16.f32 "
        "{%0,%1,%2,%3}, {%4,%5,%6,%7}, {%8,%9}, {%0,%1,%2,%3};"
        : "+f"(c[0]), "+f"(c[1]), "+f"(c[2]), "+f"(c[3])
        : "r"(a[0]), "r"(a[1]), "r"(a[2]), "r"(a[3]), "r"(b[0]), "r"(b[1]));
}
__device__ __forceinline__ uint32_t pack_h2(float v0, float v1) {
    __half h0 = __float2half_rn(v0);
    __half h1 = __float2half_rn(v1);
    return (uint32_t)__half_as_ushort(h0) | ((uint32_t)__half_as_ushort(h1) << 16);
}

// ===== GEMM: CTA 128x128, BK=64, 2 stages, 2 CTAs/SM, 8 warps (4x2), warp 32x64 ====
// TRB=true : B is [N,K] row-major (NT): B tile 128 n-rows x 128B
// TRB=false: B is [K,N] row-major (NN): B tile 64 k-rows x 256B (ldsm.trans)
#define GBM 128
#define GBN 128
#define GBK 64
#define ROWA 128               // bytes per A smem row (64 fp16)
#define ABYTES (GBM*ROWA)      // 16384
#define BOF ABYTES
#define BBYTES 16384
#define STAGEB (ABYTES + BBYTES)   // 32768
#define GEMM_SMEM (2*STAGEB)       // 65536

template <bool TRB>
__device__ __forceinline__ void stage_in(
    const __half* A, const __half* B,
    int ldA, int ldB, int m0, int n0, int k0, uint32_t sb, int tid)
{
#pragma unroll
    for (int i = 0; i < 4; ++i) {             // A: 128 rows x 8 chunks of 16B
        const int idx = tid + i * 256;
        const int r = idx >> 3, c16 = idx & 7;
        const uint32_t soff = (uint32_t)(r * ROWA + (((c16 ^ (r & 7)) << 4)));
        cp_async16(sb + soff, A + (size_t)(m0 + r) * ldA + k0 + c16 * 8);
    }
    if (TRB) {
#pragma unroll
        for (int i = 0; i < 4; ++i) {         // B: 128 n-rows x 8 chunks
            const int idx = tid + i * 256;
            const int r = idx >> 3, c16 = idx & 7;
            const uint32_t soff = (uint32_t)(r * ROWA + (((c16 ^ (r & 7)) << 4)));
            cp_async16(sb + BOF + soff, B + (size_t)(n0 + r) * ldB + k0 + c16 * 8);
        }
    } else {
#pragma unroll
        for (int i = 0; i < 4; ++i) {         // B: 64 k-rows x 16 chunks (256B rows)
            const int idx = tid + i * 256;
            const int r = idx >> 4, c16 = idx & 15;
            const uint32_t soff = (uint32_t)(r * 256 + (((c16 ^ (r & 7)) << 4)));
            cp_async16(sb + BOF + soff, B + (size_t)(k0 + r) * ldB + n0 + c16 * 8);
        }
    }
}

// MODE 1: fp16 outputs routed among q/k/v by global n / 1024 (projection)
// MODE 2: C fp32 = alpha * D / rsum[row]  (PV)
// MODE 3: P = exp(alpha*D) fp16 + per-(row,ctaX) partial sums (QK+softmax)
template <int MODE, bool TRB>
__global__ void __launch_bounds__(256, 2)
tc_gemm(const __half* __restrict__ A, const __half* __restrict__ B,
        float* __restrict__ Cf,
        __half* __restrict__ o0, __half* __restrict__ o1, __half* __restrict__ o2,
        int M, int N, int K, int ldA, int ldB,
        size_t zA, size_t zB, size_t zC,
        float alpha, const float* __restrict__ rsum, float* __restrict__ part)
{
    extern __shared__ __align__(128) char smem[];
    const uint32_t sbase = smem_u32(smem);
    const int tid = threadIdx.x;
    const int wid = tid >> 5, lane = tid & 31;
    const int wm = wid >> 1, wn = wid & 1;        // warp grid 4(m) x 2(n)
    const int z = blockIdx.z;
    const int m0 = blockIdx.y * GBM, n0 = blockIdx.x * GBN;

    A += (size_t)z * zA;  B += (size_t)z * zB;

    float acc[2][8][4];
#pragma unroll
    for (int i = 0; i < 2; ++i)
#pragma unroll
        for (int j = 0; j < 8; ++j)
#pragma unroll
            for (int q = 0; q < 4; ++q) acc[i][j][q] = 0.f;

    const int numT = K / GBK;
    stage_in<TRB>(A, B, ldA, ldB, m0, n0, 0, sbase, tid);
    cp_commit();

    // A fragment addressing (plain ldsm)
    const int a_row = wm * 32 + (lane & 15);
    const uint32_t a_rl = (uint32_t)(a_row & 7);
    const uint32_t a_hi4 = (uint32_t)(lane >> 4);
    const uint32_t a_off = (uint32_t)(a_row * ROWA);

    // B fragment addressing — NT path
    const int b_row = wn * 64 + ((lane >> 4) & 1) * 8 + (lane & 7);
    const uint32_t b_rl = (uint32_t)(b_row & 7);
    const uint32_t b_hi = (uint32_t)((lane >> 3) & 1);
    const uint32_t b_off = (uint32_t)(b_row * ROWA);

    // B fragment addressing — NN (trans) path
    const uint32_t t_klocal = (uint32_t)(((lane >> 3) & 1) * 8 + (lane & 7));
    const uint32_t t_rl = (uint32_t)(lane & 7);
    const uint32_t t_hi = (uint32_t)(lane >> 4);

    for (int t = 0; t < numT; ++t) {
        if (t + 1 < numT) {
            stage_in<TRB>(A, B, ldA, ldB, m0, n0, (t + 1) * GBK,
                          sbase + ((t + 1) & 1) * STAGEB, tid);
            cp_commit();
            cp_wait<1>();
        } else {
            cp_wait<0>();
        }
        __syncthreads();

        const uint32_t sbuf = sbase + (t & 1) * STAGEB;
#pragma unroll
        for (int kc = 0; kc < 4; ++kc) {
            uint32_t af[2][4], bf[8][2];
            const uint32_t a_x = ((((uint32_t)(kc * 2) + a_hi4) ^ a_rl) << 4);
            ldsm_x4(af[0], sbuf + a_off + a_x);
            ldsm_x4(af[1], sbuf + a_off + a_x + 16 * ROWA);

            if (TRB) {
                const uint32_t b_x = ((((uint32_t)(kc * 2) + b_hi) ^ b_rl) << 4);
                const uint32_t bb = sbuf + BOF + b_off + b_x;
                ldsm_x4(&bf[0][0], bb);
                ldsm_x4(&bf[2][0], bb + 16 * ROWA);
                ldsm_x4(&bf[4][0], bb + 32 * ROWA);
                ldsm_x4(&bf[6][0], bb + 48 * ROWA);
            } else {
                const uint32_t row_off = ((uint32_t)(kc * 16) + t_klocal) * 256;
                const uint32_t bb = sbuf + BOF + row_off;
#pragma unroll
                for (int nt = 0; nt < 4; ++nt) {
                    const uint32_t c16 = (uint32_t)(wn * 8 + nt * 2) + t_hi;
                    ldsm_x4_t(&bf[nt * 2][0], bb + ((c16 ^ t_rl) << 4));
                }
            }
#pragma unroll
            for (int mt = 0; mt < 2; ++mt)
#pragma unroll
                for (int nt = 0; nt < 8; ++nt) mma_f16(acc[mt][nt], af[mt], bf[nt]);
        }
        __syncthreads();
    }

    const int qrow = lane >> 2;
    const int qcol = (lane & 3) * 2;

    if (MODE == 3) {
        float* psum = reinterpret_cast<float*>(smem);
        float rsloc[2][2];
#pragma unroll
        for (int mt = 0; mt < 2; ++mt) { rsloc[mt][0] = 0.f; rsloc[mt][1] = 0.f; }

#pragma unroll
        for (int mt = 0; mt < 2; ++mt) {
            const int r0 = m0 + wm * 32 + mt * 16 + qrow;
#pragma unroll
            for (int nt = 0; nt < 8; ++nt) {
                const int ncol = n0 + wn * 64 + nt * 8 + qcol;
                const float* c = acc[mt][nt];
                const float e0 = __expf(alpha * c[0]);
                const float e1 = __expf(alpha * c[1]);
                const float e2 = __expf(alpha * c[2]);
                const float e3 = __expf(alpha * c[3]);
                rsloc[mt][0] += e0 + e1;
                rsloc[mt][1] += e2 + e3;
                size_t off = (size_t)z * zC + (size_t)r0 * N + ncol;
                *reinterpret_cast<uint32_t*>(o0 + off) = pack_h2(e0, e1);
                *reinterpret_cast<uint32_t*>(o0 + off + (size_t)8 * N) = pack_h2(e2, e3);
            }
        }
#pragma unroll
        for (int mt = 0; mt < 2; ++mt)
#pragma unroll
            for (int h = 0; h < 2; ++h) {
                float v = rsloc[mt][h];
                v += __shfl_xor_sync(0xffffffffu, v, 1);
                v += __shfl_xor_sync(0xffffffffu, v, 2);
                rsloc[mt][h] = v;
            }
        if ((lane & 3) == 0) {
#pragma unroll
            for (int mt = 0; mt < 2; ++mt) {
                const int lr = wm * 32 + mt * 16 + qrow;
                psum[wn * GBM + lr] = rsloc[mt][0];
                psum[wn * GBM + lr + 8] = rsloc[mt][1];
            }
        }
        __syncthreads();
        if (tid < GBM) {
            const float s = psum[tid] + psum[GBM + tid];
            part[((size_t)z * M + m0 + tid) * gridDim.x + blockIdx.x] = s;
        }
        return;
    }

#pragma unroll
    for (int mt = 0; mt < 2; ++mt) {
        const int r0 = m0 + wm * 32 + mt * 16 + qrow;
        float sc0 = alpha, sc1 = alpha;
        if (MODE == 2) {
            sc0 = alpha / __ldg(&rsum[(size_t)z * M + r0]);
            sc1 = alpha / __ldg(&rsum[(size_t)z * M + r0 + 8]);
        }
#pragma unroll
        for (int nt = 0; nt < 8; ++nt) {
            const int ncol = n0 + wn * 64 + nt * 8 + qcol;
            const float* c = acc[mt][nt];
            if (MODE == 2) {
                float* base = Cf + (size_t)z * zC;
                float2 v0 = make_float2(sc0 * c[0], sc0 * c[1]);
                float2 v1 = make_float2(sc1 * c[2], sc1 * c[3]);
                *reinterpret_cast<float2*>(base + (size_t)r0 * N + ncol) = v0;
                *reinterpret_cast<float2*>(base + (size_t)(r0 + 8) * N + ncol) = v1;
            } else {   // MODE 1
                const int sel = ncol >> 10;
                __half* D = (sel == 0) ? o0 : ((sel == 1) ? o1 : o2);
                const int cm = ncol & (DD - 1);
                size_t off = (size_t)r0 * DD + cm;
                *reinterpret_cast<uint32_t*>(D + off) = pack_h2(c[0], c[1]);
                *reinterpret_cast<uint32_t*>(D + off + (size_t)8 * DD) = pack_h2(c[2], c[3]);
            }
        }
    }
}

// ---------------- aux kernels ----------------
__global__ __launch_bounds__(256)
void conv_x(const float* __restrict__ in, __half* __restrict__ o, size_t n4)
{
    size_t i = (size_t)blockIdx.x * 256 + threadIdx.x;
    if (i >= n4) return;
    float4 v = reinterpret_cast<const float4*>(in)[i];
    reinterpret_cast<uint2*>(o)[i] = make_uint2(pack_h2(v.x, v.y), pack_h2(v.z, v.w));
}

// convert W [D,D] fp32 -> fused [K=1024, N=3072] fp16 (no transpose)
__global__ __launch_bounds__(256)
void conv_w(const float* __restrict__ Wq, const float* __restrict__ Wk,
            const float* __restrict__ Wv, __half* __restrict__ wt)
{
    const int zz = blockIdx.y;
    const float* W = (zz == 0) ? Wq : ((zz == 1) ? Wk : Wv);
    size_t i = (size_t)blockIdx.x * 256 + threadIdx.x;    // over DD*DD/4
    if (i >= (size_t)DD * DD / 4) return;
    const int k = (int)(i / (DD / 4));
    const int nq = (int)(i % (DD / 4));
    float4 v = reinterpret_cast<const float4*>(W)[i];
    uint2 pk = make_uint2(pack_h2(v.x, v.y), pack_h2(v.z, v.w));
    *reinterpret_cast<uint2*>(wt + (size_t)k * (3 * DD) + zz * DD + nq * 4) = pk;
}

__global__ __launch_bounds__(256)
void reduce_rsum(const float* __restrict__ part, float* __restrict__ rsum)
{
    const int row = blockIdx.x * 8 + (threadIdx.x >> 5);
    const int lane = threadIdx.x & 31;
    float v = part[(size_t)row * 32 + lane];
#pragma unroll
    for (int o = 16; o > 0; o >>= 1) v += __shfl_xor_sync(0xffffffffu, v, o);
    if (lane == 0) rsum[row] = v;
}

// ---------------- launch ----------------
extern "C" void kernel_launch(void* const* d_in, const int* in_sizes, int n_in,
                              void* d_out, int out_size)
{
    const float* x  = (const float*)d_in[0];
    const float* Wq = (const float*)d_in[1];
    const float* Wk = (const float*)d_in[2];
    const float* Wv = (const float*)d_in[3];
    float* out = (float*)d_out;

    __half *px, *pw, *pq, *pk, *pv, *pp;
    float *prs, *ppart;
    cudaGetSymbolAddress((void**)&px, g_x16);   cudaGetSymbolAddress((void**)&pw, g_w16);
    cudaGetSymbolAddress((void**)&pq, g_q16);   cudaGetSymbolAddress((void**)&pk, g_k16);
    cudaGetSymbolAddress((void**)&pv, g_v16);   cudaGetSymbolAddress((void**)&pp, g_p16);
    cudaGetSymbolAddress((void**)&prs, g_rsum); cudaGetSymbolAddress((void**)&ppart, g_part);

    cudaFuncSetAttribute((const void*)tc_gemm<1,false>, cudaFuncAttributeMaxDynamicSharedMemorySize, GEMM_SMEM);
    cudaFuncSetAttribute((const void*)tc_gemm<3,true>,  cudaFuncAttributeMaxDynamicSharedMemorySize, GEMM_SMEM);
    cudaFuncSetAttribute((const void*)tc_gemm<2,false>, cudaFuncAttributeMaxDynamicSharedMemorySize, GEMM_SMEM);

    // 1) convert inputs to fp16 (W without transpose: [K, 3N] fused)
    conv_x<<<(unsigned)(((size_t)MPROJ * DD / 4 + 255) / 256), 256>>>(x, px, (size_t)MPROJ * DD / 4);
    conv_w<<<dim3((unsigned)(((size_t)DD * DD / 4 + 255) / 256), 3), 256>>>(Wq, Wk, Wv, pw);

    // 2) fused QKV projection (NN: B = W [1024, 3072]) -> Q,K,V fp16
    tc_gemm<1,false><<<dim3(3 * DD / GBN, MPROJ / GBM, 1), 256, GEMM_SMEM>>>(
        px, pw, nullptr, pq, pk, pv,
        MPROJ, 3 * DD, DD, DD, 3 * DD, 0, 0, 0, 1.0f, nullptr, nullptr);

    // 3) QK^T (NT) + fused exp + row partial sums
    tc_gemm<3,true><<<dim3(SS / GBN, SS / GBM, BB), 256, GEMM_SMEM>>>(
        pq, pk, nullptr, pp, nullptr, nullptr,
        SS, SS, DD, DD, DD,
        (size_t)SS * DD, (size_t)SS * DD, (size_t)SS * SS, 1.0f / 32.0f, nullptr, ppart);

    // 4) reduce partials -> rsum
    reduce_rsum<<<BB * SS / 8, 256>>>(ppart, prs);

    // 5) out = (P @ V) / rsum per batch (NN: B = V [S, D])
    tc_gemm<2,false><<<dim3(DD / GBN, SS / GBM, BB), 256, GEMM_SMEM>>>(
        pp, pv, out, nullptr, nullptr, nullptr,
        SS, DD, SS, SS, DD,
        (size_t)SS * SS, (size_t)SS * DD, (size_t)SS * DD, 1.0f, prs, ppart);
}